// round 8
// baseline (speedup 1.0000x reference)
#include <cuda_runtime.h>
#include <cuda_fp16.h>
#include <math.h>
#include <stdint.h>

// Problem constants
#define BQ   2
#define SEQ  2048
#define DIM  1024
#define NH   16
#define HDIM 64
#define MROWS (BQ * SEQ)   // 4096

#define C63 0.984375f      // 63/64
#define CINV64 0.015625f   // 1/64

// Scratch. h = fp16 main, m = fp16 merged-residual.
__device__ __half gXh[MROWS * DIM];
__device__ __half gXm[MROWS * DIM];
__device__ __half gWh[4 * DIM * DIM];
__device__ __half gWm[4 * DIM * DIM];
__device__ __half gQh[MROWS * DIM];
__device__ __half gQm[MROWS * DIM];
__device__ __half gKh[MROWS * DIM];
__device__ __half gKm[MROWS * DIM];
__device__ __half gVh[MROWS * DIM];   // V single fp16
__device__ __half gOh[MROWS * DIM];   // attention output, single fp16
__device__ float  gPq[MROWS * DIM];   // fp32 partial: Xh*Wq_h
__device__ float  gPk[MROWS * DIM];   // fp32 partial: Xh*Wk_h

// ---------------------------------------------------------------------------
// Helpers
// ---------------------------------------------------------------------------
__device__ __forceinline__ uint32_t smem_u32(const void* p) {
    uint32_t a;
    asm("{ .reg .u64 t; cvta.to.shared.u64 t, %1; cvt.u32.u64 %0, t; }"
        : "=r"(a) : "l"(p));
    return a;
}
__device__ __forceinline__ void cp16(uint32_t dst, const void* src) {
    asm volatile("cp.async.cg.shared.global [%0], [%1], 16;"
                 :: "r"(dst), "l"(__cvta_generic_to_global(src)));
}
__device__ __forceinline__ void cp_commit() {
    asm volatile("cp.async.commit_group;" ::: "memory");
}
__device__ __forceinline__ void ldsm4(uint32_t* r, uint32_t addr) {
    asm volatile("ldmatrix.sync.aligned.m8n8.x4.shared.b16 {%0,%1,%2,%3}, [%4];"
                 : "=r"(r[0]), "=r"(r[1]), "=r"(r[2]), "=r"(r[3]) : "r"(addr));
}
__device__ __forceinline__ void ldsm4t(uint32_t* r, uint32_t addr) {
    asm volatile("ldmatrix.sync.aligned.m8n8.x4.trans.shared.b16 {%0,%1,%2,%3}, [%4];"
                 : "=r"(r[0]), "=r"(r[1]), "=r"(r[2]), "=r"(r[3]) : "r"(addr));
}
__device__ __forceinline__ void mma16816(float* c, const uint32_t* a, const uint32_t* b) {
    asm volatile(
        "mma.sync.aligned.m16n8k16.row.col.f32.f16.f16.f32 "
        "{%0,%1,%2,%3}, {%4,%5,%6,%7}, {%8,%9}, {%0,%1,%2,%3};"
        : "+f"(c[0]), "+f"(c[1]), "+f"(c[2]), "+f"(c[3])
        : "r"(a[0]), "r"(a[1]), "r"(a[2]), "r"(a[3]), "r"(b[0]), "r"(b[1]));
}
__device__ __forceinline__ uint32_t pack_h2(__half a, __half b) {
    __half2 t = __halves2half2(a, b);
    return *(uint32_t*)&t;
}
__device__ __forceinline__ uint32_t pack_f2h(float a, float b) {
    __half2 t = __halves2half2(__float2half_rn(a), __float2half_rn(b));
    return *(uint32_t*)&t;
}
// A-side split: h = fp16(x), m = fp16(h + 64*(x-h))
__device__ __forceinline__ void splitA(float f0, float f1, uint32_t& h, uint32_t& m) {
    __half h0 = __float2half_rn(f0), h1 = __float2half_rn(f1);
    float r0 = f0 - __half2float(h0), r1 = f1 - __half2float(h1);
    __half m0 = __float2half_rn(fmaf(64.f, r0, __half2float(h0)));
    __half m1 = __float2half_rn(fmaf(64.f, r1, __half2float(h1)));
    h = pack_h2(h0, h1);
    m = pack_h2(m0, m1);
}
// B-side split: h = fp16(x), m = fp16((x-h) + h/64)
__device__ __forceinline__ void splitB(float f0, float f1, uint32_t& h, uint32_t& m) {
    __half h0 = __float2half_rn(f0), h1 = __float2half_rn(f1);
    float r0 = f0 - __half2float(h0), r1 = f1 - __half2float(h1);
    __half m0 = __float2half_rn(fmaf(__half2float(h0), CINV64, r0));
    __half m1 = __float2half_rn(fmaf(__half2float(h1), CINV64, r1));
    h = pack_h2(h0, h1);
    m = pack_h2(m0, m1);
}

// ---------------------------------------------------------------------------
// Convert fp32 inputs -> fp16 h/m pairs. X: A-side. Weights: B-side.
// ---------------------------------------------------------------------------
__global__ __launch_bounds__(256) void convert_inputs(
    const float* __restrict__ X, const float* __restrict__ Wq,
    const float* __restrict__ Wk, const float* __restrict__ Wv,
    const float* __restrict__ Wo) {
    const int XQ = MROWS * DIM / 4;
    const int WQ = DIM * DIM / 4;
    const int total4 = XQ + 4 * WQ;
    for (int i = blockIdx.x * blockDim.x + threadIdx.x; i < total4;
         i += gridDim.x * blockDim.x) {
        const float* src;
        __half *dh, *dm;
        bool aside;
        if (i < XQ) {
            int e = i * 4;
            src = X + e; dh = gXh + e; dm = gXm + e; aside = true;
        } else {
            int t = i - XQ;
            int w = t / WQ;
            int off = (t - w * WQ) * 4;
            src = (w == 0) ? Wq + off : (w == 1) ? Wk + off
                  : (w == 2) ? Wv + off : Wo + off;
            dh = gWh + (size_t)w * DIM * DIM + off;
            dm = gWm + (size_t)w * DIM * DIM + off;
            aside = false;
        }
        float4 v = *(const float4*)src;
        uint32_t h0, m0, h1, m1;
        if (aside) {
            splitA(v.x, v.y, h0, m0);
            splitA(v.z, v.w, h1, m1);
        } else {
            splitB(v.x, v.y, h0, m0);
            splitB(v.z, v.w, h1, m1);
        }
        ((uint32_t*)dh)[0] = h0;
        ((uint32_t*)dh)[1] = h1;
        ((uint32_t*)dm)[0] = m0;
        ((uint32_t*)dm)[1] = m1;
    }
}

// ---------------------------------------------------------------------------
// Single-term fp16 GEMM: 128x128 CTA tile, K-step 32, 8 warps (64x32 tiles),
// 3-stage cp.async, 2 CTAs/SM. Output modes:
//   MODE_P  : write raw fp32 product (no bias)          [projection pass 1]
//   MODE_V  : write single fp16                          [V projection]
//   MODE_RA : C63*Pin + acc + bias -> splitA fp16 pair   [Q pass 2]
//   MODE_RB : C63*Pin + acc + bias -> splitB fp16 pair   [K pass 2]
//   MODE_OUT: acc + bias -> fp32                         [output projection]
// ---------------------------------------------------------------------------
#define MODE_P   0
#define MODE_V   1
#define MODE_RA  2
#define MODE_RB  3
#define MODE_OUT 4

#define STAGE_BYTES 32768
#define SM_BH 16384
#define GEMM_SMEM (3 * STAGE_BYTES)

__device__ __forceinline__ void fill1(uint32_t sbuf,
                                      const __half* __restrict__ A,
                                      const __half* __restrict__ B,
                                      int row0, int col0, int kt, int tid) {
#pragma unroll
    for (int i = 0; i < 2; ++i) {  // A: 512 16B chunks
        int lin = tid + i * 256;
        int m = lin >> 2, c = lin & 3;
        cp16(sbuf + m * 128 + ((c ^ (m & 7)) << 4),
             A + (size_t)(row0 + m) * DIM + kt + c * 8);
    }
#pragma unroll
    for (int i = 0; i < 2; ++i) {  // B: 512 16B chunks
        int lin = tid + i * 256;
        int k = lin >> 4, c = lin & 15;
        cp16(sbuf + SM_BH + k * 256 + ((c >> 3) << 7) +
                 (((c & 7) ^ (k & 7)) << 4),
             B + (size_t)(kt + k) * DIM + col0 + c * 8);
    }
}

template <int MODE>
__device__ __forceinline__ void gemm1_body(
    const __half* __restrict__ Ag, const __half* __restrict__ Bg,
    const float* __restrict__ bias, const float* __restrict__ Pin,
    float* __restrict__ Yf, __half* __restrict__ Yh, __half* __restrict__ Ym) {
    extern __shared__ __align__(1024) char smem[];
    const uint32_t sb = smem_u32(smem);
    const int tid = threadIdx.x;
    const int row0 = blockIdx.y * 128, col0 = blockIdx.x * 128;
    const int lane = tid & 31, wid = tid >> 5;
    const int wm = wid & 1, wn = wid >> 1;
    const int q = lane >> 3, r = lane & 7;
    const int arow = (q & 1) * 8 + r;
    const int aq = q >> 1;

    float acc[4][4][4];
#pragma unroll
    for (int mt = 0; mt < 4; ++mt)
#pragma unroll
        for (int nt = 0; nt < 4; ++nt)
#pragma unroll
            for (int e = 0; e < 4; ++e) acc[mt][nt][e] = 0.f;

    fill1(sb, Ag, Bg, row0, col0, 0, tid);
    cp_commit();
    fill1(sb + STAGE_BYTES, Ag, Bg, row0, col0, 32, tid);
    cp_commit();

    for (int s = 0; s < 32; ++s) {
        const int buf = s % 3;
        if (s + 2 < 32) {
            fill1(sb + ((s + 2) % 3) * STAGE_BYTES, Ag, Bg, row0, col0,
                  (s + 2) * 32, tid);
            cp_commit();
            asm volatile("cp.async.wait_group 2;" ::: "memory");
        } else if (s + 1 < 32) {
            asm volatile("cp.async.wait_group 1;" ::: "memory");
        } else {
            asm volatile("cp.async.wait_group 0;" ::: "memory");
        }
        __syncthreads();

        const uint32_t sA = sb + buf * STAGE_BYTES;
        const uint32_t sBh = sA + SM_BH;

#pragma unroll
        for (int k16 = 0; k16 < 2; ++k16) {
            uint32_t bh[8];
            {
                const int krow = k16 * 16 + (q & 1) * 8 + r;
#pragma unroll
                for (int g2 = 0; g2 < 2; ++g2) {
                    int cg = wn * 4 + g2 * 2 + (q >> 1);
                    uint32_t baddr = krow * 256 + ((cg >> 3) << 7) +
                                     (((cg & 7) ^ (krow & 7)) << 4);
                    ldsm4t(&bh[g2 * 4], sBh + baddr);
                }
            }
            uint32_t ah[4][4];
#pragma unroll
            for (int mt = 0; mt < 4; ++mt) {
                int row = wm * 64 + mt * 16 + arow;
                int c1 = k16 * 2 + aq;
                ldsm4(ah[mt], sA + row * 128 + ((c1 ^ r) << 4));
            }
#pragma unroll
            for (int mt = 0; mt < 4; ++mt)
#pragma unroll
                for (int nt = 0; nt < 4; ++nt)
                    mma16816(acc[mt][nt], ah[mt], &bh[(nt >> 1) * 4 + (nt & 1) * 2]);
        }
        __syncthreads();
    }

    const int cg = lane >> 2, ct = lane & 3;
#pragma unroll
    for (int mt = 0; mt < 4; ++mt) {
        int r0 = row0 + wm * 64 + mt * 16 + cg;
#pragma unroll
        for (int nt = 0; nt < 4; ++nt) {
            int col = col0 + wn * 32 + nt * 8 + ct * 2;
            float v00 = acc[mt][nt][0], v01 = acc[mt][nt][1];
            float v10 = acc[mt][nt][2], v11 = acc[mt][nt][3];
            if (MODE == MODE_P) {
                *(float2*)(Yf + (size_t)r0 * DIM + col) = make_float2(v00, v01);
                *(float2*)(Yf + (size_t)(r0 + 8) * DIM + col) = make_float2(v10, v11);
            } else if (MODE == MODE_V) {
                *(uint32_t*)&Yh[(size_t)r0 * DIM + col] = pack_f2h(v00, v01);
                *(uint32_t*)&Yh[(size_t)(r0 + 8) * DIM + col] = pack_f2h(v10, v11);
            } else if (MODE == MODE_OUT) {
                float b0 = bias[col], b1 = bias[col + 1];
                *(float2*)(Yf + (size_t)r0 * DIM + col) =
                    make_float2(v00 + b0, v01 + b1);
                *(float2*)(Yf + (size_t)(r0 + 8) * DIM + col) =
                    make_float2(v10 + b0, v11 + b1);
            } else {  // MODE_RA / MODE_RB
                float b0 = bias[col], b1 = bias[col + 1];
                float2 p0 = *(const float2*)(Pin + (size_t)r0 * DIM + col);
                float2 p1 = *(const float2*)(Pin + (size_t)(r0 + 8) * DIM + col);
                v00 = fmaf(p0.x, C63, v00) + b0;
                v01 = fmaf(p0.y, C63, v01) + b1;
                v10 = fmaf(p1.x, C63, v10) + b0;
                v11 = fmaf(p1.y, C63, v11) + b1;
                uint32_t h, m;
                if (MODE == MODE_RA) splitA(v00, v01, h, m); else splitB(v00, v01, h, m);
                *(uint32_t*)&Yh[(size_t)r0 * DIM + col] = h;
                *(uint32_t*)&Ym[(size_t)r0 * DIM + col] = m;
                if (MODE == MODE_RA) splitA(v10, v11, h, m); else splitB(v10, v11, h, m);
                *(uint32_t*)&Yh[(size_t)(r0 + 8) * DIM + col] = h;
                *(uint32_t*)&Ym[(size_t)(r0 + 8) * DIM + col] = m;
            }
        }
    }
}

__global__ __launch_bounds__(256, 2) void proj_hi() {
    const int z = blockIdx.z;
    if (z == 0)
        gemm1_body<MODE_P>(gXh, gWh, nullptr, nullptr, gPq, nullptr, nullptr);
    else if (z == 1)
        gemm1_body<MODE_P>(gXh, gWh + (size_t)DIM * DIM, nullptr, nullptr, gPk,
                           nullptr, nullptr);
    else
        gemm1_body<MODE_V>(gXh, gWh + (size_t)2 * DIM * DIM, nullptr, nullptr,
                           nullptr, gVh, nullptr);
}

__global__ __launch_bounds__(256, 2) void proj_res(const float* __restrict__ bq,
                                                   const float* __restrict__ bk) {
    const int z = blockIdx.z;
    if (z == 0)
        gemm1_body<MODE_RA>(gXm, gWm, bq, gPq, nullptr, gQh, gQm);
    else
        gemm1_body<MODE_RB>(gXm, gWm + (size_t)DIM * DIM, bk, gPk, nullptr,
                            gKh, gKm);
}

__global__ __launch_bounds__(256, 2) void out_mma(const float* __restrict__ bo,
                                                  float* __restrict__ out) {
    gemm1_body<MODE_OUT>(gOh, gWh + (size_t)3 * DIM * DIM, bo, nullptr, out,
                         nullptr, nullptr);
}

// ---------------------------------------------------------------------------
// Flash attention. QK^T: merged 2-MMA (logit accuracy). PV: single fp16 MMA.
// 8 warps; warp w owns 16 query rows. Hard causal (soft mask underflows).
// Diagonal tile: warp-uniform triangular skip of fully-masked strips.
// smem: Qh/Qm 32KB + 2 stages of {Kh,Km,Vh} 48KB.
// ---------------------------------------------------------------------------
#define A_ST0 32768
#define A_STAGE 49152
#define ATTN_SMEM (32768 + 2 * 49152)

__global__ __launch_bounds__(256, 1) void attn_mma() {
    extern __shared__ __align__(1024) char smem[];
    const uint32_t sb = smem_u32(smem);
    const int tid = threadIdx.x;
    const int lane = tid & 31, w = tid >> 5;
    const int q = lane >> 3, r = lane & 7;
    const int g = lane >> 2, t = lane & 3;
    const int it = 15 - (int)blockIdx.x;  // heavy tiles first
    const int bh = blockIdx.y;
    const int b = bh >> 4, h = bh & 15;
    const int i0 = it * 128;
    const float slope = exp2f(-0.5f * (float)(h + 1));
    const int qrow_base = b * SEQ + i0;
    const int hcol = h * HDIM;

    // ---- fill Q (h+m), 32KB ----
#pragma unroll
    for (int i = 0; i < 8; ++i) {
        int lin = tid + i * 256;
        int tz = lin >> 10;
        int rem = lin & 1023;
        int m = rem >> 3, c = rem & 7;
        const __half* src =
            (tz ? gQm : gQh) + (size_t)(qrow_base + m) * DIM + hcol + c * 8;
        cp16(sb + tz * 16384 + m * 128 + ((c ^ (m & 7)) << 4), src);
    }
    // ---- fill K/V stage 0: Kh, Km, Vh (48KB) ----
    {
        const int krow_base = b * SEQ;
#pragma unroll
        for (int i = 0; i < 12; ++i) {
            int lin = tid + i * 256;
            int tz = lin >> 10;  // 0=Kh 1=Km 2=Vh
            int rem = lin & 1023;
            int m = rem >> 3, c = rem & 7;
            const __half* src =
                ((tz == 0) ? gKh : (tz == 1) ? gKm : gVh) +
                (size_t)(krow_base + m) * DIM + hcol + c * 8;
            cp16(sb + A_ST0 + tz * 16384 + m * 128 + ((c ^ (m & 7)) << 4), src);
        }
    }
    cp_commit();

    float o[8][4];
#pragma unroll
    for (int nt = 0; nt < 8; ++nt)
#pragma unroll
        for (int e = 0; e < 4; ++e) o[nt][e] = 0.f;
    float m0 = -1e30f, m1 = -1e30f, l0 = 0.f, l1 = 0.f;
    uint32_t qh[4][4], qm[4][4];

    int buf = 0;
    for (int jt = 0; jt <= it; ++jt) {
        if (jt < it) {
            const int krow_base = b * SEQ + (jt + 1) * 128;
            const uint32_t st = sb + A_ST0 + (buf ^ 1) * A_STAGE;
#pragma unroll
            for (int i = 0; i < 12; ++i) {
                int lin = tid + i * 256;
                int tz = lin >> 10;
                int rem = lin & 1023;
                int m = rem >> 3, c = rem & 7;
                const __half* src =
                    ((tz == 0) ? gKh : (tz == 1) ? gKm : gVh) +
                    (size_t)(krow_base + m) * DIM + hcol + c * 8;
                cp16(st + tz * 16384 + m * 128 + ((c ^ (m & 7)) << 4), src);
            }
            cp_commit();
            asm volatile("cp.async.wait_group 1;" ::: "memory");
        } else {
            asm volatile("cp.async.wait_group 0;" ::: "memory");
        }
        __syncthreads();

        if (jt == 0) {  // hoist Q fragments
#pragma unroll
            for (int k16 = 0; k16 < 4; ++k16) {
                int row = w * 16 + (q & 1) * 8 + r;
                int c = k16 * 2 + (q >> 1);
                uint32_t ad = sb + row * 128 + ((c ^ r) << 4);
                ldsm4(qh[k16], ad);
                ldsm4(qm[k16], ad + 16384);
            }
        }

        const uint32_t sk = sb + A_ST0 + buf * A_STAGE;
        const uint32_t sv = sk + 32768;
        const bool diag = (jt == it);

        // ---- S = Q K^T (merged 2-MMA); skip fully-masked strips on diag ----
        float s[16][4];
#pragma unroll
        for (int nt16 = 0; nt16 < 8; ++nt16) {
            if (diag && nt16 > w) {
#pragma unroll
                for (int e = 0; e < 4; ++e) {
                    s[2 * nt16][e] = 0.f;
                    s[2 * nt16 + 1][e] = 0.f;
                }
                continue;
            }
            float s1[2][4], s2[2][4];
#pragma unroll
            for (int e = 0; e < 4; ++e) {
                s1[0][e] = s1[1][e] = 0.f;
                s2[0][e] = s2[1][e] = 0.f;
            }
            const int row = nt16 * 16 + (q >> 1) * 8 + r;
#pragma unroll
            for (int k16 = 0; k16 < 4; ++k16) {
                const int c = k16 * 2 + (q & 1);
                uint32_t ad = sk + row * 128 + ((c ^ r) << 4);
                uint32_t kh[4], km[4];
                ldsm4(kh, ad);
                ldsm4(km, ad + 16384);
                mma16816(s1[0], qh[k16], kh);
                mma16816(s2[0], qm[k16], km);
                mma16816(s1[1], qh[k16], kh + 2);
                mma16816(s2[1], qm[k16], km + 2);
            }
#pragma unroll
            for (int e = 0; e < 4; ++e) {
                s[2 * nt16][e] = fmaf(s1[0][e], C63, s2[0][e]);
                s[2 * nt16 + 1][e] = fmaf(s1[1][e], C63, s2[1][e]);
            }
        }

        // ---- online softmax ----
        const int j0 = jt * 128;
        const int rowg0 = i0 + w * 16 + g;
        const int rowg1 = rowg0 + 8;
        float mx0 = -1e30f, mx1 = -1e30f;
#pragma unroll
        for (int nt = 0; nt < 16; ++nt) {
            const int jc = j0 + nt * 8 + 2 * t;
            const float c0 = (float)jc;
            s[nt][0] = s[nt][0] * 0.125f - slope * c0;
            s[nt][1] = s[nt][1] * 0.125f - slope * (c0 + 1.f);
            s[nt][2] = s[nt][2] * 0.125f - slope * c0;
            s[nt][3] = s[nt][3] * 0.125f - slope * (c0 + 1.f);
            if (diag) {
                if (jc > rowg0) s[nt][0] = -1e30f;
                if (jc + 1 > rowg0) s[nt][1] = -1e30f;
                if (jc > rowg1) s[nt][2] = -1e30f;
                if (jc + 1 > rowg1) s[nt][3] = -1e30f;
            }
            mx0 = fmaxf(mx0, fmaxf(s[nt][0], s[nt][1]));
            mx1 = fmaxf(mx1, fmaxf(s[nt][2], s[nt][3]));
        }
        mx0 = fmaxf(mx0, __shfl_xor_sync(0xffffffffu, mx0, 1, 4));
        mx0 = fmaxf(mx0, __shfl_xor_sync(0xffffffffu, mx0, 2, 4));
        mx1 = fmaxf(mx1, __shfl_xor_sync(0xffffffffu, mx1, 1, 4));
        mx1 = fmaxf(mx1, __shfl_xor_sync(0xffffffffu, mx1, 2, 4));
        const float mn0 = fmaxf(m0, mx0), mn1 = fmaxf(m1, mx1);
        const float cr0 = __expf(m0 - mn0), cr1 = __expf(m1 - mn1);
        m0 = mn0;
        m1 = mn1;
        float sum0 = 0.f, sum1 = 0.f;
#pragma unroll
        for (int nt = 0; nt < 16; ++nt) {
            s[nt][0] = __expf(s[nt][0] - mn0);
            s[nt][1] = __expf(s[nt][1] - mn0);
            s[nt][2] = __expf(s[nt][2] - mn1);
            s[nt][3] = __expf(s[nt][3] - mn1);
            sum0 += s[nt][0] + s[nt][1];
            sum1 += s[nt][2] + s[nt][3];
        }
        sum0 += __shfl_xor_sync(0xffffffffu, sum0, 1, 4);
        sum0 += __shfl_xor_sync(0xffffffffu, sum0, 2, 4);
        sum1 += __shfl_xor_sync(0xffffffffu, sum1, 1, 4);
        sum1 += __shfl_xor_sync(0xffffffffu, sum1, 2, 4);
        l0 = l0 * cr0 + sum0;
        l1 = l1 * cr1 + sum1;
#pragma unroll
        for (int nt = 0; nt < 8; ++nt) {
            o[nt][0] *= cr0;
            o[nt][1] *= cr0;
            o[nt][2] *= cr1;
            o[nt][3] *= cr1;
        }

        // ---- O += P V (single fp16 MMA); skip zero P strips on diag ----
#pragma unroll
        for (int k16 = 0; k16 < 8; ++k16) {
            if (diag && k16 > w) continue;  // p == 0 exactly (masked)
            uint32_t ph[4];
            ph[0] = pack_f2h(s[2 * k16][0], s[2 * k16][1]);
            ph[1] = pack_f2h(s[2 * k16][2], s[2 * k16][3]);
            ph[2] = pack_f2h(s[2 * k16 + 1][0], s[2 * k16 + 1][1]);
            ph[3] = pack_f2h(s[2 * k16 + 1][2], s[2 * k16 + 1][3]);
            const int row = k16 * 16 + (q & 1) * 8 + r;
#pragma unroll
            for (int cgp = 0; cgp < 4; ++cgp) {
                const int c = cgp * 2 + (q >> 1);
                uint32_t ad = sv + row * 128 + ((c ^ r) << 4);
                uint32_t vh[4];
                ldsm4t(vh, ad);
                mma16816(o[cgp * 2], ph, vh);
                mma16816(o[cgp * 2 + 1], ph, vh + 2);
            }
        }
        __syncthreads();
        buf ^= 1;
    }

    // ---- epilogue: normalize, store single fp16 ----
    const float inv0 = 1.f / l0, inv1 = 1.f / l1;
    const size_t orow0 = (size_t)(qrow_base + w * 16 + g) * DIM + hcol;
    const size_t orow1 = orow0 + (size_t)8 * DIM;
#pragma unroll
    for (int nt = 0; nt < 8; ++nt) {
        const int col = nt * 8 + 2 * t;
        *(uint32_t*)&gOh[orow0 + col] = pack_f2h(o[nt][0] * inv0, o[nt][1] * inv0);
        *(uint32_t*)&gOh[orow1 + col] = pack_f2h(o[nt][2] * inv1, o[nt][3] * inv1);
    }
}

// ---------------------------------------------------------------------------
extern "C" void kernel_launch(void* const* d_in, const int* in_sizes, int n_in,
                              void* d_out, int out_size) {
    const float* X  = (const float*)d_in[0];
    const float* Wq = (const float*)d_in[1];
    const float* bq = (const float*)d_in[2];
    const float* Wk = (const float*)d_in[3];
    const float* bk = (const float*)d_in[4];
    const float* Wv = (const float*)d_in[5];
    const float* Wo = (const float*)d_in[6];
    const float* bo = (const float*)d_in[7];
    float* out = (float*)d_out;

    cudaFuncSetAttribute(proj_hi, cudaFuncAttributeMaxDynamicSharedMemorySize, GEMM_SMEM);
    cudaFuncSetAttribute(proj_res, cudaFuncAttributeMaxDynamicSharedMemorySize, GEMM_SMEM);
    cudaFuncSetAttribute(out_mma, cudaFuncAttributeMaxDynamicSharedMemorySize, GEMM_SMEM);
    cudaFuncSetAttribute(attn_mma, cudaFuncAttributeMaxDynamicSharedMemorySize, ATTN_SMEM);

    convert_inputs<<<2048, 256>>>(X, Wq, Wk, Wv, Wo);
    proj_hi<<<dim3(DIM / 128, MROWS / 128, 3), 256, GEMM_SMEM>>>();
    proj_res<<<dim3(DIM / 128, MROWS / 128, 2), 256, GEMM_SMEM>>>(bq, bk);
    attn_mma<<<dim3(SEQ / 128, BQ * NH), 256, ATTN_SMEM>>>();
    out_mma<<<dim3(DIM / 128, MROWS / 128, 1), 256, GEMM_SMEM>>>(bo, out);
}

// round 9
// speedup vs baseline: 1.0477x; 1.0477x over previous
#include <cuda_runtime.h>
#include <cuda_fp16.h>
#include <math.h>
#include <stdint.h>

// Problem constants
#define BQ   2
#define SEQ  2048
#define DIM  1024
#define NH   16
#define HDIM 64
#define MROWS (BQ * SEQ)   // 4096

#define C63 0.984375f      // 63/64
#define CINV64 0.015625f   // 1/64

// Scratch. h = fp16 main, m = fp16 merged-residual (only where 2-term used).
__device__ __half gXh[MROWS * DIM];
__device__ __half gXm[MROWS * DIM];
__device__ __half gWh[4 * DIM * DIM];
__device__ __half gWm[4 * DIM * DIM];
__device__ __half gQh[MROWS * DIM];
__device__ __half gQm[MROWS * DIM];
__device__ __half gKh[MROWS * DIM];
__device__ __half gKm[MROWS * DIM];
__device__ __half gVh[MROWS * DIM];   // V single fp16 (quantized by PV anyway)
__device__ __half gOh[MROWS * DIM];   // attention output, single fp16

// ---------------------------------------------------------------------------
// Helpers
// ---------------------------------------------------------------------------
__device__ __forceinline__ uint32_t smem_u32(const void* p) {
    uint32_t a;
    asm("{ .reg .u64 t; cvta.to.shared.u64 t, %1; cvt.u32.u64 %0, t; }"
        : "=r"(a) : "l"(p));
    return a;
}
__device__ __forceinline__ void cp16(uint32_t dst, const void* src) {
    asm volatile("cp.async.cg.shared.global [%0], [%1], 16;"
                 :: "r"(dst), "l"(__cvta_generic_to_global(src)));
}
__device__ __forceinline__ void cp_commit() {
    asm volatile("cp.async.commit_group;" ::: "memory");
}
__device__ __forceinline__ void ldsm4(uint32_t* r, uint32_t addr) {
    asm volatile("ldmatrix.sync.aligned.m8n8.x4.shared.b16 {%0,%1,%2,%3}, [%4];"
                 : "=r"(r[0]), "=r"(r[1]), "=r"(r[2]), "=r"(r[3]) : "r"(addr));
}
__device__ __forceinline__ void ldsm4t(uint32_t* r, uint32_t addr) {
    asm volatile("ldmatrix.sync.aligned.m8n8.x4.trans.shared.b16 {%0,%1,%2,%3}, [%4];"
                 : "=r"(r[0]), "=r"(r[1]), "=r"(r[2]), "=r"(r[3]) : "r"(addr));
}
__device__ __forceinline__ void mma16816(float* c, const uint32_t* a, const uint32_t* b) {
    asm volatile(
        "mma.sync.aligned.m16n8k16.row.col.f32.f16.f16.f32 "
        "{%0,%1,%2,%3}, {%4,%5,%6,%7}, {%8,%9}, {%0,%1,%2,%3};"
        : "+f"(c[0]), "+f"(c[1]), "+f"(c[2]), "+f"(c[3])
        : "r"(a[0]), "r"(a[1]), "r"(a[2]), "r"(a[3]), "r"(b[0]), "r"(b[1]));
}
__device__ __forceinline__ uint32_t pack_h2(__half a, __half b) {
    __half2 t = __halves2half2(a, b);
    return *(uint32_t*)&t;
}
__device__ __forceinline__ uint32_t pack_f2h(float a, float b) {
    __half2 t = __halves2half2(__float2half_rn(a), __float2half_rn(b));
    return *(uint32_t*)&t;
}
// A-side split: h = fp16(x), m = fp16(h + 64*(x-h))
__device__ __forceinline__ void splitA(float f0, float f1, uint32_t& h, uint32_t& m) {
    __half h0 = __float2half_rn(f0), h1 = __float2half_rn(f1);
    float r0 = f0 - __half2float(h0), r1 = f1 - __half2float(h1);
    __half m0 = __float2half_rn(fmaf(64.f, r0, __half2float(h0)));
    __half m1 = __float2half_rn(fmaf(64.f, r1, __half2float(h1)));
    h = pack_h2(h0, h1);
    m = pack_h2(m0, m1);
}
// B-side split: h = fp16(x), m = fp16((x-h) + h/64)
__device__ __forceinline__ void splitB(float f0, float f1, uint32_t& h, uint32_t& m) {
    __half h0 = __float2half_rn(f0), h1 = __float2half_rn(f1);
    float r0 = f0 - __half2float(h0), r1 = f1 - __half2float(h1);
    __half m0 = __float2half_rn(fmaf(__half2float(h0), CINV64, r0));
    __half m1 = __float2half_rn(fmaf(__half2float(h1), CINV64, r1));
    h = pack_h2(h0, h1);
    m = pack_h2(m0, m1);
}

// ---------------------------------------------------------------------------
// Convert fp32 inputs -> fp16 h/m pairs. X: A-side. Weights: B-side.
// ---------------------------------------------------------------------------
__global__ __launch_bounds__(256) void convert_inputs(
    const float* __restrict__ X, const float* __restrict__ Wq,
    const float* __restrict__ Wk, const float* __restrict__ Wv,
    const float* __restrict__ Wo) {
    const int XQ = MROWS * DIM / 4;
    const int WQ = DIM * DIM / 4;
    const int total4 = XQ + 4 * WQ;
    for (int i = blockIdx.x * blockDim.x + threadIdx.x; i < total4;
         i += gridDim.x * blockDim.x) {
        const float* src;
        __half *dh, *dm;
        bool aside;
        if (i < XQ) {
            int e = i * 4;
            src = X + e; dh = gXh + e; dm = gXm + e; aside = true;
        } else {
            int t = i - XQ;
            int w = t / WQ;
            int off = (t - w * WQ) * 4;
            src = (w == 0) ? Wq + off : (w == 1) ? Wk + off
                  : (w == 2) ? Wv + off : Wo + off;
            dh = gWh + (size_t)w * DIM * DIM + off;
            dm = gWm + (size_t)w * DIM * DIM + off;
            aside = false;
        }
        float4 v = *(const float4*)src;
        uint32_t h0, m0, h1, m1;
        if (aside) {
            splitA(v.x, v.y, h0, m0);
            splitA(v.z, v.w, h1, m1);
        } else {
            splitB(v.x, v.y, h0, m0);
            splitB(v.z, v.w, h1, m1);
        }
        ((uint32_t*)dh)[0] = h0;
        ((uint32_t*)dh)[1] = h1;
        ((uint32_t*)dm)[0] = m0;
        ((uint32_t*)dm)[1] = m1;
    }
}

// ---------------------------------------------------------------------------
// Tensor-core GEMM. TERMS=2: merged 2-MMA (C = C1*63/64 + C2). TERMS=1:
// single fp16 MMA. 128x128 CTA tile, K-step 32, 8 warps (64x32 tiles),
// 3-stage cp.async. OMODE: 0=fp32+bias, 1=splitA pair, 2=splitB pair, 3=fp16.
// ---------------------------------------------------------------------------
#define STAGE_BYTES 32768
#define SM_BH 16384
#define SM_BM 24576
#define GEMM_SMEM (3 * STAGE_BYTES)

template <int TERMS>
__device__ __forceinline__ void gemm_fill(uint32_t sbuf,
                                          const __half* __restrict__ Ah,
                                          const __half* __restrict__ Am,
                                          const __half* __restrict__ Bh,
                                          const __half* __restrict__ Bm,
                                          int row0, int col0, int kt, int tid) {
    if (TERMS == 2) {
#pragma unroll
        for (int i = 0; i < 4; ++i) {
            int lin = tid + i * 256;
            int m = lin >> 3, c = lin & 7;
            const __half* src =
                ((c < 4) ? Ah : Am) + (size_t)(row0 + m) * DIM + kt + (c & 3) * 8;
            cp16(sbuf + m * 128 + ((c ^ (m & 7)) << 4), src);
        }
#pragma unroll
        for (int i = 0; i < 4; ++i) {
            int lin = tid + i * 256;
            int tile = lin >> 9, rem = lin & 511;
            int k = rem >> 4, c = rem & 15;
            const __half* src =
                (tile ? Bm : Bh) + (size_t)(kt + k) * DIM + col0 + c * 8;
            cp16(sbuf + (tile ? SM_BM : SM_BH) + k * 256 +
                     ((c >> 3) << 7) + (((c & 7) ^ (k & 7)) << 4),
                 src);
        }
    } else {
#pragma unroll
        for (int i = 0; i < 2; ++i) {
            int lin = tid + i * 256;
            int m = lin >> 2, c = lin & 3;
            cp16(sbuf + m * 128 + ((c ^ (m & 7)) << 4),
                 Ah + (size_t)(row0 + m) * DIM + kt + c * 8);
        }
#pragma unroll
        for (int i = 0; i < 2; ++i) {
            int lin = tid + i * 256;
            int k = lin >> 4, c = lin & 15;
            cp16(sbuf + SM_BH + k * 256 + ((c >> 3) << 7) +
                     (((c & 7) ^ (k & 7)) << 4),
                 Bh + (size_t)(kt + k) * DIM + col0 + c * 8);
        }
    }
}

template <int TERMS, int OMODE>
__device__ __forceinline__ void mma_gemm_body(
    const __half* __restrict__ Ah_g, const __half* __restrict__ Am_g,
    const __half* __restrict__ Bh_g, const __half* __restrict__ Bm_g,
    const float* __restrict__ bias, float* __restrict__ Yf,
    __half* __restrict__ Yh, __half* __restrict__ Ym) {
    extern __shared__ __align__(1024) char smem[];
    const uint32_t sb = smem_u32(smem);
    const int tid = threadIdx.x;
    const int row0 = blockIdx.y * 128, col0 = blockIdx.x * 128;
    const int lane = tid & 31, wid = tid >> 5;
    const int wm = wid & 1, wn = wid >> 1;
    const int q = lane >> 3, r = lane & 7;
    const int arow = (q & 1) * 8 + r;
    const int aq = q >> 1;

    float acc1[4][4][4], acc2[TERMS == 2 ? 4 : 1][TERMS == 2 ? 4 : 1][4];
#pragma unroll
    for (int mt = 0; mt < 4; ++mt)
#pragma unroll
        for (int nt = 0; nt < 4; ++nt)
#pragma unroll
            for (int e = 0; e < 4; ++e) acc1[mt][nt][e] = 0.f;
    if (TERMS == 2) {
#pragma unroll
        for (int mt = 0; mt < 4; ++mt)
#pragma unroll
            for (int nt = 0; nt < 4; ++nt)
#pragma unroll
                for (int e = 0; e < 4; ++e) acc2[mt][nt][e] = 0.f;
    }

    gemm_fill<TERMS>(sb, Ah_g, Am_g, Bh_g, Bm_g, row0, col0, 0, tid);
    cp_commit();
    gemm_fill<TERMS>(sb + STAGE_BYTES, Ah_g, Am_g, Bh_g, Bm_g, row0, col0, 32, tid);
    cp_commit();

    for (int s = 0; s < 32; ++s) {
        const int buf = s % 3;
        if (s + 2 < 32) {
            gemm_fill<TERMS>(sb + ((s + 2) % 3) * STAGE_BYTES, Ah_g, Am_g,
                             Bh_g, Bm_g, row0, col0, (s + 2) * 32, tid);
            cp_commit();
            asm volatile("cp.async.wait_group 2;" ::: "memory");
        } else if (s + 1 < 32) {
            asm volatile("cp.async.wait_group 1;" ::: "memory");
        } else {
            asm volatile("cp.async.wait_group 0;" ::: "memory");
        }
        __syncthreads();

        const uint32_t sA = sb + buf * STAGE_BYTES;
        const uint32_t sBh = sA + SM_BH;
        const uint32_t sBm = sA + SM_BM;

#pragma unroll
        for (int k16 = 0; k16 < 2; ++k16) {
            uint32_t bh[8], bm[8];
            {
                const int krow = k16 * 16 + (q & 1) * 8 + r;
#pragma unroll
                for (int g2 = 0; g2 < 2; ++g2) {
                    int cg = wn * 4 + g2 * 2 + (q >> 1);
                    uint32_t baddr = krow * 256 + ((cg >> 3) << 7) +
                                     (((cg & 7) ^ (krow & 7)) << 4);
                    ldsm4t(&bh[g2 * 4], sBh + baddr);
                    if (TERMS == 2) ldsm4t(&bm[g2 * 4], sBm + baddr);
                }
            }
            uint32_t ah[4][4];
#pragma unroll
            for (int mt = 0; mt < 4; ++mt) {
                int row = wm * 64 + mt * 16 + arow;
                int c1 = k16 * 2 + aq;
                ldsm4(ah[mt], sA + row * 128 + ((c1 ^ r) << 4));
            }
#pragma unroll
            for (int mt = 0; mt < 4; ++mt)
#pragma unroll
                for (int nt = 0; nt < 4; ++nt)
                    mma16816(acc1[mt][nt], ah[mt], &bh[(nt >> 1) * 4 + (nt & 1) * 2]);
            if (TERMS == 2) {
                uint32_t am[4][4];
#pragma unroll
                for (int mt = 0; mt < 4; ++mt) {
                    int row = wm * 64 + mt * 16 + arow;
                    int c2 = 4 + k16 * 2 + aq;
                    ldsm4(am[mt], sA + row * 128 + ((c2 ^ r) << 4));
                }
#pragma unroll
                for (int mt = 0; mt < 4; ++mt)
#pragma unroll
                    for (int nt = 0; nt < 4; ++nt)
                        mma16816(acc2[mt][nt], am[mt], &bm[(nt >> 1) * 4 + (nt & 1) * 2]);
            }
        }
        __syncthreads();
    }

    const int cg = lane >> 2, ct = lane & 3;
#pragma unroll
    for (int mt = 0; mt < 4; ++mt) {
        int r0 = row0 + wm * 64 + mt * 16 + cg;
#pragma unroll
        for (int nt = 0; nt < 4; ++nt) {
            int col = col0 + wn * 32 + nt * 8 + ct * 2;
            float b0 = bias ? bias[col] : 0.f;
            float b1 = bias ? bias[col + 1] : 0.f;
            float v00, v01, v10, v11;
            if (TERMS == 2) {
                v00 = fmaf(acc1[mt][nt][0], C63, acc2[mt][nt][0]) + b0;
                v01 = fmaf(acc1[mt][nt][1], C63, acc2[mt][nt][1]) + b1;
                v10 = fmaf(acc1[mt][nt][2], C63, acc2[mt][nt][2]) + b0;
                v11 = fmaf(acc1[mt][nt][3], C63, acc2[mt][nt][3]) + b1;
            } else {
                v00 = acc1[mt][nt][0] + b0;
                v01 = acc1[mt][nt][1] + b1;
                v10 = acc1[mt][nt][2] + b0;
                v11 = acc1[mt][nt][3] + b1;
            }
            if (OMODE == 0) {
                *(float2*)(Yf + (size_t)r0 * DIM + col) = make_float2(v00, v01);
                *(float2*)(Yf + (size_t)(r0 + 8) * DIM + col) = make_float2(v10, v11);
            } else if (OMODE == 3) {
                *(uint32_t*)&Yh[(size_t)r0 * DIM + col] = pack_f2h(v00, v01);
                *(uint32_t*)&Yh[(size_t)(r0 + 8) * DIM + col] = pack_f2h(v10, v11);
            } else {
                uint32_t h, m;
                if (OMODE == 1) splitA(v00, v01, h, m); else splitB(v00, v01, h, m);
                *(uint32_t*)&Yh[(size_t)r0 * DIM + col] = h;
                *(uint32_t*)&Ym[(size_t)r0 * DIM + col] = m;
                if (OMODE == 1) splitA(v10, v11, h, m); else splitB(v10, v11, h, m);
                *(uint32_t*)&Yh[(size_t)(r0 + 8) * DIM + col] = h;
                *(uint32_t*)&Ym[(size_t)(r0 + 8) * DIM + col] = m;
            }
        }
    }
}

__global__ __launch_bounds__(256, 1) void qkv_mma(const float* __restrict__ bq,
                                                  const float* __restrict__ bk) {
    const int z = blockIdx.z;
    const __half* Bh = gWh + (size_t)z * DIM * DIM;
    const __half* Bm = gWm + (size_t)z * DIM * DIM;
    if (z == 0) {
        mma_gemm_body<2, 1>(gXh, gXm, Bh, Bm, bq, nullptr, gQh, gQm);
    } else if (z == 1) {
        mma_gemm_body<2, 2>(gXh, gXm, Bh, Bm, bk, nullptr, gKh, gKm);
    } else {
        mma_gemm_body<1, 3>(gXh, nullptr, Bh, nullptr, nullptr, nullptr, gVh, nullptr);
    }
}

__global__ __launch_bounds__(256, 1) void out_mma(const float* __restrict__ bo,
                                                  float* __restrict__ out) {
    mma_gemm_body<1, 0>(gOh, nullptr, gWh + (size_t)3 * DIM * DIM, nullptr,
                        bo, out, nullptr, nullptr);
}

// ---------------------------------------------------------------------------
// Flash attention. QK^T merged 2-MMA, PV single fp16 MMA, hard causal.
// ALiBi window: weights with slope*j > 100 beyond the row max underflow fp32
// exp() in the reference too -> skip whole j-tiles per head, bit-exact.
// Diagonal tile: warp-uniform triangular strip skip.
// ---------------------------------------------------------------------------
#define A_ST0 32768
#define A_STAGE 49152
#define ATTN_SMEM (32768 + 2 * 49152)

__global__ __launch_bounds__(256, 1) void attn_mma() {
    extern __shared__ __align__(1024) char smem[];
    const uint32_t sb = smem_u32(smem);
    const int tid = threadIdx.x;
    const int lane = tid & 31, w = tid >> 5;
    const int q = lane >> 3, r = lane & 7;
    const int g = lane >> 2, t = lane & 3;
    const int it = 15 - (int)blockIdx.x;  // heavy tiles first
    const int bh = blockIdx.y;
    const int b = bh >> 4, h = bh & 15;
    const int i0 = it * 128;
    const float slope = exp2f(-0.5f * (float)(h + 1));
    const int qrow_base = b * SEQ + i0;
    const int hcol = h * HDIM;

    // ALiBi window: number of j-tiles that can contribute (see header comment)
    const int Jt_cap = min(16, (int)(100.f / slope) / 128 + 1);
    const int Jt = min(it + 1, Jt_cap);   // loop runs jt = 0 .. Jt-1

    // ---- fill Q (h+m), 32KB ----
#pragma unroll
    for (int i = 0; i < 8; ++i) {
        int lin = tid + i * 256;
        int tz = lin >> 10;
        int rem = lin & 1023;
        int m = rem >> 3, c = rem & 7;
        const __half* src =
            (tz ? gQm : gQh) + (size_t)(qrow_base + m) * DIM + hcol + c * 8;
        cp16(sb + tz * 16384 + m * 128 + ((c ^ (m & 7)) << 4), src);
    }
    // ---- fill K/V stage 0: Kh, Km, Vh (48KB) ----
    {
        const int krow_base = b * SEQ;
#pragma unroll
        for (int i = 0; i < 12; ++i) {
            int lin = tid + i * 256;
            int tz = lin >> 10;  // 0=Kh 1=Km 2=Vh
            int rem = lin & 1023;
            int m = rem >> 3, c = rem & 7;
            const __half* src =
                ((tz == 0) ? gKh : (tz == 1) ? gKm : gVh) +
                (size_t)(krow_base + m) * DIM + hcol + c * 8;
            cp16(sb + A_ST0 + tz * 16384 + m * 128 + ((c ^ (m & 7)) << 4), src);
        }
    }
    cp_commit();

    float o[8][4];
#pragma unroll
    for (int nt = 0; nt < 8; ++nt)
#pragma unroll
        for (int e = 0; e < 4; ++e) o[nt][e] = 0.f;
    float m0 = -1e30f, m1 = -1e30f, l0 = 0.f, l1 = 0.f;
    uint32_t qh[4][4], qm[4][4];

    int buf = 0;
    for (int jt = 0; jt < Jt; ++jt) {
        if (jt + 1 < Jt) {
            const int krow_base = b * SEQ + (jt + 1) * 128;
            const uint32_t st = sb + A_ST0 + (buf ^ 1) * A_STAGE;
#pragma unroll
            for (int i = 0; i < 12; ++i) {
                int lin = tid + i * 256;
                int tz = lin >> 10;
                int rem = lin & 1023;
                int m = rem >> 3, c = rem & 7;
                const __half* src =
                    ((tz == 0) ? gKh : (tz == 1) ? gKm : gVh) +
                    (size_t)(krow_base + m) * DIM + hcol + c * 8;
                cp16(st + tz * 16384 + m * 128 + ((c ^ (m & 7)) << 4), src);
            }
            cp_commit();
            asm volatile("cp.async.wait_group 1;" ::: "memory");
        } else {
            asm volatile("cp.async.wait_group 0;" ::: "memory");
        }
        __syncthreads();

        if (jt == 0) {  // hoist Q fragments
#pragma unroll
            for (int k16 = 0; k16 < 4; ++k16) {
                int row = w * 16 + (q & 1) * 8 + r;
                int c = k16 * 2 + (q >> 1);
                uint32_t ad = sb + row * 128 + ((c ^ r) << 4);
                ldsm4(qh[k16], ad);
                ldsm4(qm[k16], ad + 16384);
            }
        }

        const uint32_t sk = sb + A_ST0 + buf * A_STAGE;
        const uint32_t sv = sk + 32768;
        const bool diag = (jt == it);

        // ---- S = Q K^T (merged 2-MMA); triangular strip skip on diag ----
        float s[16][4];
#pragma unroll
        for (int nt16 = 0; nt16 < 8; ++nt16) {
            if (diag && nt16 > w) {
#pragma unroll
                for (int e = 0; e < 4; ++e) {
                    s[2 * nt16][e] = 0.f;
                    s[2 * nt16 + 1][e] = 0.f;
                }
                continue;
            }
            float s1[2][4], s2[2][4];
#pragma unroll
            for (int e = 0; e < 4; ++e) {
                s1[0][e] = s1[1][e] = 0.f;
                s2[0][e] = s2[1][e] = 0.f;
            }
            const int row = nt16 * 16 + (q >> 1) * 8 + r;
#pragma unroll
            for (int k16 = 0; k16 < 4; ++k16) {
                const int c = k16 * 2 + (q & 1);
                uint32_t ad = sk + row * 128 + ((c ^ r) << 4);
                uint32_t kh[4], km[4];
                ldsm4(kh, ad);
                ldsm4(km, ad + 16384);
                mma16816(s1[0], qh[k16], kh);
                mma16816(s2[0], qm[k16], km);
                mma16816(s1[1], qh[k16], kh + 2);
                mma16816(s2[1], qm[k16], km + 2);
            }
#pragma unroll
            for (int e = 0; e < 4; ++e) {
                s[2 * nt16][e] = fmaf(s1[0][e], C63, s2[0][e]);
                s[2 * nt16 + 1][e] = fmaf(s1[1][e], C63, s2[1][e]);
            }
        }

        // ---- online softmax ----
        const int j0 = jt * 128;
        const int rowg0 = i0 + w * 16 + g;
        const int rowg1 = rowg0 + 8;
        float mx0 = -1e30f, mx1 = -1e30f;
#pragma unroll
        for (int nt = 0; nt < 16; ++nt) {
            const int jc = j0 + nt * 8 + 2 * t;
            const float c0 = (float)jc;
            s[nt][0] = s[nt][0] * 0.125f - slope * c0;
            s[nt][1] = s[nt][1] * 0.125f - slope * (c0 + 1.f);
            s[nt][2] = s[nt][2] * 0.125f - slope * c0;
            s[nt][3] = s[nt][3] * 0.125f - slope * (c0 + 1.f);
            if (diag) {
                if (jc > rowg0) s[nt][0] = -1e30f;
                if (jc + 1 > rowg0) s[nt][1] = -1e30f;
                if (jc > rowg1) s[nt][2] = -1e30f;
                if (jc + 1 > rowg1) s[nt][3] = -1e30f;
            }
            mx0 = fmaxf(mx0, fmaxf(s[nt][0], s[nt][1]));
            mx1 = fmaxf(mx1, fmaxf(s[nt][2], s[nt][3]));
        }
        mx0 = fmaxf(mx0, __shfl_xor_sync(0xffffffffu, mx0, 1, 4));
        mx0 = fmaxf(mx0, __shfl_xor_sync(0xffffffffu, mx0, 2, 4));
        mx1 = fmaxf(mx1, __shfl_xor_sync(0xffffffffu, mx1, 1, 4));
        mx1 = fmaxf(mx1, __shfl_xor_sync(0xffffffffu, mx1, 2, 4));
        const float mn0 = fmaxf(m0, mx0), mn1 = fmaxf(m1, mx1);
        const float cr0 = __expf(m0 - mn0), cr1 = __expf(m1 - mn1);
        m0 = mn0;
        m1 = mn1;
        float sum0 = 0.f, sum1 = 0.f;
#pragma unroll
        for (int nt = 0; nt < 16; ++nt) {
            s[nt][0] = __expf(s[nt][0] - mn0);
            s[nt][1] = __expf(s[nt][1] - mn0);
            s[nt][2] = __expf(s[nt][2] - mn1);
            s[nt][3] = __expf(s[nt][3] - mn1);
            sum0 += s[nt][0] + s[nt][1];
            sum1 += s[nt][2] + s[nt][3];
        }
        sum0 += __shfl_xor_sync(0xffffffffu, sum0, 1, 4);
        sum0 += __shfl_xor_sync(0xffffffffu, sum0, 2, 4);
        sum1 += __shfl_xor_sync(0xffffffffu, sum1, 1, 4);
        sum1 += __shfl_xor_sync(0xffffffffu, sum1, 2, 4);
        l0 = l0 * cr0 + sum0;
        l1 = l1 * cr1 + sum1;
#pragma unroll
        for (int nt = 0; nt < 8; ++nt) {
            o[nt][0] *= cr0;
            o[nt][1] *= cr0;
            o[nt][2] *= cr1;
            o[nt][3] *= cr1;
        }

        // ---- O += P V (single fp16 MMA); skip zero P strips on diag ----
#pragma unroll
        for (int k16 = 0; k16 < 8; ++k16) {
            if (diag && k16 > w) continue;  // p == 0 exactly (masked)
            uint32_t ph[4];
            ph[0] = pack_f2h(s[2 * k16][0], s[2 * k16][1]);
            ph[1] = pack_f2h(s[2 * k16][2], s[2 * k16][3]);
            ph[2] = pack_f2h(s[2 * k16 + 1][0], s[2 * k16 + 1][1]);
            ph[3] = pack_f2h(s[2 * k16 + 1][2], s[2 * k16 + 1][3]);
            const int row = k16 * 16 + (q & 1) * 8 + r;
#pragma unroll
            for (int cgp = 0; cgp < 4; ++cgp) {
                const int c = cgp * 2 + (q >> 1);
                uint32_t ad = sv + row * 128 + ((c ^ r) << 4);
                uint32_t vh[4];
                ldsm4t(vh, ad);
                mma16816(o[cgp * 2], ph, vh);
                mma16816(o[cgp * 2 + 1], ph, vh + 2);
            }
        }
        __syncthreads();
        buf ^= 1;
    }

    // ---- epilogue: normalize, store single fp16 ----
    const float inv0 = 1.f / l0, inv1 = 1.f / l1;
    const size_t orow0 = (size_t)(qrow_base + w * 16 + g) * DIM + hcol;
    const size_t orow1 = orow0 + (size_t)8 * DIM;
#pragma unroll
    for (int nt = 0; nt < 8; ++nt) {
        const int col = nt * 8 + 2 * t;
        *(uint32_t*)&gOh[orow0 + col] = pack_f2h(o[nt][0] * inv0, o[nt][1] * inv0);
        *(uint32_t*)&gOh[orow1 + col] = pack_f2h(o[nt][2] * inv1, o[nt][3] * inv1);
    }
}

// ---------------------------------------------------------------------------
extern "C" void kernel_launch(void* const* d_in, const int* in_sizes, int n_in,
                              void* d_out, int out_size) {
    const float* X  = (const float*)d_in[0];
    const float* Wq = (const float*)d_in[1];
    const float* bq = (const float*)d_in[2];
    const float* Wk = (const float*)d_in[3];
    const float* bk = (const float*)d_in[4];
    const float* Wv = (const float*)d_in[5];
    const float* Wo = (const float*)d_in[6];
    const float* bo = (const float*)d_in[7];
    float* out = (float*)d_out;

    cudaFuncSetAttribute(qkv_mma, cudaFuncAttributeMaxDynamicSharedMemorySize, GEMM_SMEM);
    cudaFuncSetAttribute(out_mma, cudaFuncAttributeMaxDynamicSharedMemorySize, GEMM_SMEM);
    cudaFuncSetAttribute(attn_mma, cudaFuncAttributeMaxDynamicSharedMemorySize, ATTN_SMEM);

    convert_inputs<<<2048, 256>>>(X, Wq, Wk, Wv, Wo);
    qkv_mma<<<dim3(DIM / 128, MROWS / 128, 3), 256, GEMM_SMEM>>>(bq, bk);
    attn_mma<<<dim3(SEQ / 128, BQ * NH), 256, ATTN_SMEM>>>();
    out_mma<<<dim3(DIM / 128, MROWS / 128, 1), 256, GEMM_SMEM>>>(bo, out);
}

// round 10
// speedup vs baseline: 1.1476x; 1.0954x over previous
#include <cuda_runtime.h>
#include <cuda_fp16.h>
#include <math.h>
#include <stdint.h>

// Problem constants
#define BQ   2
#define SEQ  2048
#define DIM  1024
#define NH   16
#define HDIM 64
#define MROWS (BQ * SEQ)   // 4096

#define C63 0.984375f      // 63/64
#define CINV64 0.015625f   // 1/64

// Scratch. h = fp16 main, m = fp16 merged-residual (weights/X only).
__device__ __half gXh[MROWS * DIM];
__device__ __half gXm[MROWS * DIM];
__device__ __half gWh[4 * DIM * DIM];
__device__ __half gWm[4 * DIM * DIM];
__device__ __half gQh[MROWS * DIM];   // Q single fp16 (accurate pre-quant)
__device__ __half gKh[MROWS * DIM];   // K single fp16 (accurate pre-quant)
__device__ __half gVh[MROWS * DIM];   // V single fp16
__device__ __half gOh[MROWS * DIM];   // attention output, single fp16

// ---------------------------------------------------------------------------
// Helpers
// ---------------------------------------------------------------------------
__device__ __forceinline__ uint32_t smem_u32(const void* p) {
    uint32_t a;
    asm("{ .reg .u64 t; cvta.to.shared.u64 t, %1; cvt.u32.u64 %0, t; }"
        : "=r"(a) : "l"(p));
    return a;
}
__device__ __forceinline__ void cp16(uint32_t dst, const void* src) {
    asm volatile("cp.async.cg.shared.global [%0], [%1], 16;"
                 :: "r"(dst), "l"(__cvta_generic_to_global(src)));
}
__device__ __forceinline__ void cp_commit() {
    asm volatile("cp.async.commit_group;" ::: "memory");
}
__device__ __forceinline__ void ldsm4(uint32_t* r, uint32_t addr) {
    asm volatile("ldmatrix.sync.aligned.m8n8.x4.shared.b16 {%0,%1,%2,%3}, [%4];"
                 : "=r"(r[0]), "=r"(r[1]), "=r"(r[2]), "=r"(r[3]) : "r"(addr));
}
__device__ __forceinline__ void ldsm4t(uint32_t* r, uint32_t addr) {
    asm volatile("ldmatrix.sync.aligned.m8n8.x4.trans.shared.b16 {%0,%1,%2,%3}, [%4];"
                 : "=r"(r[0]), "=r"(r[1]), "=r"(r[2]), "=r"(r[3]) : "r"(addr));
}
__device__ __forceinline__ void mma16816(float* c, const uint32_t* a, const uint32_t* b) {
    asm volatile(
        "mma.sync.aligned.m16n8k16.row.col.f32.f16.f16.f32 "
        "{%0,%1,%2,%3}, {%4,%5,%6,%7}, {%8,%9}, {%0,%1,%2,%3};"
        : "+f"(c[0]), "+f"(c[1]), "+f"(c[2]), "+f"(c[3])
        : "r"(a[0]), "r"(a[1]), "r"(a[2]), "r"(a[3]), "r"(b[0]), "r"(b[1]));
}
__device__ __forceinline__ uint32_t pack_h2(__half a, __half b) {
    __half2 t = __halves2half2(a, b);
    return *(uint32_t*)&t;
}
__device__ __forceinline__ uint32_t pack_f2h(float a, float b) {
    __half2 t = __halves2half2(__float2half_rn(a), __float2half_rn(b));
    return *(uint32_t*)&t;
}
// A-side split: h = fp16(x), m = fp16(h + 64*(x-h))
__device__ __forceinline__ void splitA(float f0, float f1, uint32_t& h, uint32_t& m) {
    __half h0 = __float2half_rn(f0), h1 = __float2half_rn(f1);
    float r0 = f0 - __half2float(h0), r1 = f1 - __half2float(h1);
    __half m0 = __float2half_rn(fmaf(64.f, r0, __half2float(h0)));
    __half m1 = __float2half_rn(fmaf(64.f, r1, __half2float(h1)));
    h = pack_h2(h0, h1);
    m = pack_h2(m0, m1);
}
// B-side split: h = fp16(x), m = fp16((x-h) + h/64)
__device__ __forceinline__ void splitB(float f0, float f1, uint32_t& h, uint32_t& m) {
    __half h0 = __float2half_rn(f0), h1 = __float2half_rn(f1);
    float r0 = f0 - __half2float(h0), r1 = f1 - __half2float(h1);
    __half m0 = __float2half_rn(fmaf(__half2float(h0), CINV64, r0));
    __half m1 = __float2half_rn(fmaf(__half2float(h1), CINV64, r1));
    h = pack_h2(h0, h1);
    m = pack_h2(m0, m1);
}

// ---------------------------------------------------------------------------
// Convert fp32 inputs -> fp16 h/m pairs. X: A-side. Weights: B-side.
// ---------------------------------------------------------------------------
__global__ __launch_bounds__(256) void convert_inputs(
    const float* __restrict__ X, const float* __restrict__ Wq,
    const float* __restrict__ Wk, const float* __restrict__ Wv,
    const float* __restrict__ Wo) {
    const int XQ = MROWS * DIM / 4;
    const int WQ = DIM * DIM / 4;
    const int total4 = XQ + 4 * WQ;
    for (int i = blockIdx.x * blockDim.x + threadIdx.x; i < total4;
         i += gridDim.x * blockDim.x) {
        const float* src;
        __half *dh, *dm;
        bool aside;
        if (i < XQ) {
            int e = i * 4;
            src = X + e; dh = gXh + e; dm = gXm + e; aside = true;
        } else {
            int t = i - XQ;
            int w = t / WQ;
            int off = (t - w * WQ) * 4;
            src = (w == 0) ? Wq + off : (w == 1) ? Wk + off
                  : (w == 2) ? Wv + off : Wo + off;
            dh = gWh + (size_t)w * DIM * DIM + off;
            dm = gWm + (size_t)w * DIM * DIM + off;
            aside = false;
        }
        float4 v = *(const float4*)src;
        uint32_t h0, m0, h1, m1;
        if (aside) {
            splitA(v.x, v.y, h0, m0);
            splitA(v.z, v.w, h1, m1);
        } else {
            splitB(v.x, v.y, h0, m0);
            splitB(v.z, v.w, h1, m1);
        }
        ((uint32_t*)dh)[0] = h0;
        ((uint32_t*)dh)[1] = h1;
        ((uint32_t*)dm)[0] = m0;
        ((uint32_t*)dm)[1] = m1;
    }
}

// ---------------------------------------------------------------------------
// Tensor-core GEMM. TERMS=2: merged 2-MMA (C = C1*63/64 + C2). TERMS=1:
// single fp16 MMA. 128x128 CTA tile, K-step 32, 8 warps (64x32 tiles),
// 3-stage cp.async. OMODE: 0=fp32+bias, 3=single fp16 (+bias).
// ---------------------------------------------------------------------------
#define STAGE_BYTES 32768
#define SM_BH 16384
#define SM_BM 24576
#define GEMM_SMEM (3 * STAGE_BYTES)

template <int TERMS>
__device__ __forceinline__ void gemm_fill(uint32_t sbuf,
                                          const __half* __restrict__ Ah,
                                          const __half* __restrict__ Am,
                                          const __half* __restrict__ Bh,
                                          const __half* __restrict__ Bm,
                                          int row0, int col0, int kt, int tid) {
    if (TERMS == 2) {
#pragma unroll
        for (int i = 0; i < 4; ++i) {
            int lin = tid + i * 256;
            int m = lin >> 3, c = lin & 7;
            const __half* src =
                ((c < 4) ? Ah : Am) + (size_t)(row0 + m) * DIM + kt + (c & 3) * 8;
            cp16(sbuf + m * 128 + ((c ^ (m & 7)) << 4), src);
        }
#pragma unroll
        for (int i = 0; i < 4; ++i) {
            int lin = tid + i * 256;
            int tile = lin >> 9, rem = lin & 511;
            int k = rem >> 4, c = rem & 15;
            const __half* src =
                (tile ? Bm : Bh) + (size_t)(kt + k) * DIM + col0 + c * 8;
            cp16(sbuf + (tile ? SM_BM : SM_BH) + k * 256 +
                     ((c >> 3) << 7) + (((c & 7) ^ (k & 7)) << 4),
                 src);
        }
    } else {
#pragma unroll
        for (int i = 0; i < 2; ++i) {
            int lin = tid + i * 256;
            int m = lin >> 2, c = lin & 3;
            cp16(sbuf + m * 128 + ((c ^ (m & 7)) << 4),
                 Ah + (size_t)(row0 + m) * DIM + kt + c * 8);
        }
#pragma unroll
        for (int i = 0; i < 2; ++i) {
            int lin = tid + i * 256;
            int k = lin >> 4, c = lin & 15;
            cp16(sbuf + SM_BH + k * 256 + ((c >> 3) << 7) +
                     (((c & 7) ^ (k & 7)) << 4),
                 Bh + (size_t)(kt + k) * DIM + col0 + c * 8);
        }
    }
}

template <int TERMS, int OMODE>
__device__ __forceinline__ void mma_gemm_body(
    const __half* __restrict__ Ah_g, const __half* __restrict__ Am_g,
    const __half* __restrict__ Bh_g, const __half* __restrict__ Bm_g,
    const float* __restrict__ bias, float* __restrict__ Yf,
    __half* __restrict__ Yh) {
    extern __shared__ __align__(1024) char smem[];
    const uint32_t sb = smem_u32(smem);
    const int tid = threadIdx.x;
    const int row0 = blockIdx.y * 128, col0 = blockIdx.x * 128;
    const int lane = tid & 31, wid = tid >> 5;
    const int wm = wid & 1, wn = wid >> 1;
    const int q = lane >> 3, r = lane & 7;
    const int arow = (q & 1) * 8 + r;
    const int aq = q >> 1;

    float acc1[4][4][4], acc2[TERMS == 2 ? 4 : 1][TERMS == 2 ? 4 : 1][4];
#pragma unroll
    for (int mt = 0; mt < 4; ++mt)
#pragma unroll
        for (int nt = 0; nt < 4; ++nt)
#pragma unroll
            for (int e = 0; e < 4; ++e) acc1[mt][nt][e] = 0.f;
    if (TERMS == 2) {
#pragma unroll
        for (int mt = 0; mt < 4; ++mt)
#pragma unroll
            for (int nt = 0; nt < 4; ++nt)
#pragma unroll
                for (int e = 0; e < 4; ++e) acc2[mt][nt][e] = 0.f;
    }

    gemm_fill<TERMS>(sb, Ah_g, Am_g, Bh_g, Bm_g, row0, col0, 0, tid);
    cp_commit();
    gemm_fill<TERMS>(sb + STAGE_BYTES, Ah_g, Am_g, Bh_g, Bm_g, row0, col0, 32, tid);
    cp_commit();

    for (int s = 0; s < 32; ++s) {
        const int buf = s % 3;
        if (s + 2 < 32) {
            gemm_fill<TERMS>(sb + ((s + 2) % 3) * STAGE_BYTES, Ah_g, Am_g,
                             Bh_g, Bm_g, row0, col0, (s + 2) * 32, tid);
            cp_commit();
            asm volatile("cp.async.wait_group 2;" ::: "memory");
        } else if (s + 1 < 32) {
            asm volatile("cp.async.wait_group 1;" ::: "memory");
        } else {
            asm volatile("cp.async.wait_group 0;" ::: "memory");
        }
        __syncthreads();

        const uint32_t sA = sb + buf * STAGE_BYTES;
        const uint32_t sBh = sA + SM_BH;
        const uint32_t sBm = sA + SM_BM;

#pragma unroll
        for (int k16 = 0; k16 < 2; ++k16) {
            uint32_t bh[8], bm[8];
            {
                const int krow = k16 * 16 + (q & 1) * 8 + r;
#pragma unroll
                for (int g2 = 0; g2 < 2; ++g2) {
                    int cg = wn * 4 + g2 * 2 + (q >> 1);
                    uint32_t baddr = krow * 256 + ((cg >> 3) << 7) +
                                     (((cg & 7) ^ (krow & 7)) << 4);
                    ldsm4t(&bh[g2 * 4], sBh + baddr);
                    if (TERMS == 2) ldsm4t(&bm[g2 * 4], sBm + baddr);
                }
            }
            uint32_t ah[4][4];
#pragma unroll
            for (int mt = 0; mt < 4; ++mt) {
                int row = wm * 64 + mt * 16 + arow;
                int c1 = k16 * 2 + aq;
                ldsm4(ah[mt], sA + row * 128 + ((c1 ^ r) << 4));
            }
#pragma unroll
            for (int mt = 0; mt < 4; ++mt)
#pragma unroll
                for (int nt = 0; nt < 4; ++nt)
                    mma16816(acc1[mt][nt], ah[mt], &bh[(nt >> 1) * 4 + (nt & 1) * 2]);
            if (TERMS == 2) {
                uint32_t am[4][4];
#pragma unroll
                for (int mt = 0; mt < 4; ++mt) {
                    int row = wm * 64 + mt * 16 + arow;
                    int c2 = 4 + k16 * 2 + aq;
                    ldsm4(am[mt], sA + row * 128 + ((c2 ^ r) << 4));
                }
#pragma unroll
                for (int mt = 0; mt < 4; ++mt)
#pragma unroll
                    for (int nt = 0; nt < 4; ++nt)
                        mma16816(acc2[mt][nt], am[mt], &bm[(nt >> 1) * 4 + (nt & 1) * 2]);
            }
        }
        __syncthreads();
    }

    const int cg = lane >> 2, ct = lane & 3;
#pragma unroll
    for (int mt = 0; mt < 4; ++mt) {
        int r0 = row0 + wm * 64 + mt * 16 + cg;
#pragma unroll
        for (int nt = 0; nt < 4; ++nt) {
            int col = col0 + wn * 32 + nt * 8 + ct * 2;
            float b0 = bias ? bias[col] : 0.f;
            float b1 = bias ? bias[col + 1] : 0.f;
            float v00, v01, v10, v11;
            if (TERMS == 2) {
                v00 = fmaf(acc1[mt][nt][0], C63, acc2[mt][nt][0]) + b0;
                v01 = fmaf(acc1[mt][nt][1], C63, acc2[mt][nt][1]) + b1;
                v10 = fmaf(acc1[mt][nt][2], C63, acc2[mt][nt][2]) + b0;
                v11 = fmaf(acc1[mt][nt][3], C63, acc2[mt][nt][3]) + b1;
            } else {
                v00 = acc1[mt][nt][0] + b0;
                v01 = acc1[mt][nt][1] + b1;
                v10 = acc1[mt][nt][2] + b0;
                v11 = acc1[mt][nt][3] + b1;
            }
            if (OMODE == 0) {
                *(float2*)(Yf + (size_t)r0 * DIM + col) = make_float2(v00, v01);
                *(float2*)(Yf + (size_t)(r0 + 8) * DIM + col) = make_float2(v10, v11);
            } else {  // OMODE == 3: single fp16
                *(uint32_t*)&Yh[(size_t)r0 * DIM + col] = pack_f2h(v00, v01);
                *(uint32_t*)&Yh[(size_t)(r0 + 8) * DIM + col] = pack_f2h(v10, v11);
            }
        }
    }
}

__global__ __launch_bounds__(256, 1) void qkv_mma(const float* __restrict__ bq,
                                                  const float* __restrict__ bk) {
    const int z = blockIdx.z;
    const __half* Bh = gWh + (size_t)z * DIM * DIM;
    const __half* Bm = gWm + (size_t)z * DIM * DIM;
    if (z == 0) {
        mma_gemm_body<2, 3>(gXh, gXm, Bh, Bm, bq, nullptr, gQh);
    } else if (z == 1) {
        mma_gemm_body<2, 3>(gXh, gXm, Bh, Bm, bk, nullptr, gKh);
    } else {
        mma_gemm_body<1, 3>(gXh, nullptr, Bh, nullptr, nullptr, nullptr, gVh);
    }
}

__global__ __launch_bounds__(256, 1) void out_mma(const float* __restrict__ bo,
                                                  float* __restrict__ out) {
    mma_gemm_body<1, 0>(gOh, nullptr, gWh + (size_t)3 * DIM * DIM, nullptr,
                        bo, out, nullptr);
}

// ---------------------------------------------------------------------------
// Flash attention. QK^T: single fp16 MMA (q,k accurate pre-quantization).
// PV: single fp16 MMA. Hard causal (soft mask underflows fp32 exp).
// ALiBi window: j-tiles with slope*j > 100 beyond row max underflow -> skip.
// Diagonal tile: warp-uniform triangular strip skip.
// smem: Qh 16KB + 2 stages of {Kh,Vh} 32KB = 80KB.
// ---------------------------------------------------------------------------
#define A_ST0 16384
#define A_STAGE 32768
#define ATTN_SMEM (16384 + 2 * 32768)

__global__ __launch_bounds__(256, 1) void attn_mma() {
    extern __shared__ __align__(1024) char smem[];
    const uint32_t sb = smem_u32(smem);
    const int tid = threadIdx.x;
    const int lane = tid & 31, w = tid >> 5;
    const int q = lane >> 3, r = lane & 7;
    const int g = lane >> 2, t = lane & 3;
    const int it = 15 - (int)blockIdx.x;  // heavy tiles first
    const int bh = blockIdx.y;
    const int b = bh >> 4, h = bh & 15;
    const int i0 = it * 128;
    const float slope = exp2f(-0.5f * (float)(h + 1));
    const int qrow_base = b * SEQ + i0;
    const int hcol = h * HDIM;

    // ALiBi window (bit-exact: skipped weights underflow fp32 exp)
    const int Jt_cap = min(16, (int)(100.f / slope) / 128 + 1);
    const int Jt = min(it + 1, Jt_cap);

    // ---- fill Q (single fp16, 16KB) ----
#pragma unroll
    for (int i = 0; i < 4; ++i) {
        int lin = tid + i * 256;
        int m = lin >> 3, c = lin & 7;
        cp16(sb + m * 128 + ((c ^ (m & 7)) << 4),
             gQh + (size_t)(qrow_base + m) * DIM + hcol + c * 8);
    }
    // ---- fill K/V stage 0: Kh + Vh (32KB) ----
    {
        const int krow_base = b * SEQ;
#pragma unroll
        for (int i = 0; i < 8; ++i) {
            int lin = tid + i * 256;
            int tz = lin >> 10;  // 0=Kh 1=Vh
            int rem = lin & 1023;
            int m = rem >> 3, c = rem & 7;
            const __half* src = (tz ? gVh : gKh) +
                                (size_t)(krow_base + m) * DIM + hcol + c * 8;
            cp16(sb + A_ST0 + tz * 16384 + m * 128 + ((c ^ (m & 7)) << 4), src);
        }
    }
    cp_commit();

    float o[8][4];
#pragma unroll
    for (int nt = 0; nt < 8; ++nt)
#pragma unroll
        for (int e = 0; e < 4; ++e) o[nt][e] = 0.f;
    float m0 = -1e30f, m1 = -1e30f, l0 = 0.f, l1 = 0.f;
    uint32_t qh[4][4];

    int buf = 0;
    for (int jt = 0; jt < Jt; ++jt) {
        if (jt + 1 < Jt) {
            const int krow_base = b * SEQ + (jt + 1) * 128;
            const uint32_t st = sb + A_ST0 + (buf ^ 1) * A_STAGE;
#pragma unroll
            for (int i = 0; i < 8; ++i) {
                int lin = tid + i * 256;
                int tz = lin >> 10;
                int rem = lin & 1023;
                int m = rem >> 3, c = rem & 7;
                const __half* src = (tz ? gVh : gKh) +
                                    (size_t)(krow_base + m) * DIM + hcol + c * 8;
                cp16(st + tz * 16384 + m * 128 + ((c ^ (m & 7)) << 4), src);
            }
            cp_commit();
            asm volatile("cp.async.wait_group 1;" ::: "memory");
        } else {
            asm volatile("cp.async.wait_group 0;" ::: "memory");
        }
        __syncthreads();

        if (jt == 0) {  // hoist Q fragments
#pragma unroll
            for (int k16 = 0; k16 < 4; ++k16) {
                int row = w * 16 + (q & 1) * 8 + r;
                int c = k16 * 2 + (q >> 1);
                ldsm4(qh[k16], sb + row * 128 + ((c ^ r) << 4));
            }
        }

        const uint32_t sk = sb + A_ST0 + buf * A_STAGE;
        const uint32_t sv = sk + 16384;
        const bool diag = (jt == it);

        // ---- S = Q K^T (single fp16 MMA); triangular strip skip on diag ----
        float s[16][4];
#pragma unroll
        for (int nt16 = 0; nt16 < 8; ++nt16) {
            if (diag && nt16 > w) {
#pragma unroll
                for (int e = 0; e < 4; ++e) {
                    s[2 * nt16][e] = 0.f;
                    s[2 * nt16 + 1][e] = 0.f;
                }
                continue;
            }
#pragma unroll
            for (int e = 0; e < 4; ++e) {
                s[2 * nt16][e] = 0.f;
                s[2 * nt16 + 1][e] = 0.f;
            }
            const int row = nt16 * 16 + (q >> 1) * 8 + r;
#pragma unroll
            for (int k16 = 0; k16 < 4; ++k16) {
                const int c = k16 * 2 + (q & 1);
                uint32_t kh[4];
                ldsm4(kh, sk + row * 128 + ((c ^ r) << 4));
                mma16816(s[2 * nt16], qh[k16], kh);
                mma16816(s[2 * nt16 + 1], qh[k16], kh + 2);
            }
        }

        // ---- online softmax ----
        const int j0 = jt * 128;
        const int rowg0 = i0 + w * 16 + g;
        const int rowg1 = rowg0 + 8;
        float mx0 = -1e30f, mx1 = -1e30f;
#pragma unroll
        for (int nt = 0; nt < 16; ++nt) {
            const int jc = j0 + nt * 8 + 2 * t;
            const float c0 = (float)jc;
            s[nt][0] = s[nt][0] * 0.125f - slope * c0;
            s[nt][1] = s[nt][1] * 0.125f - slope * (c0 + 1.f);
            s[nt][2] = s[nt][2] * 0.125f - slope * c0;
            s[nt][3] = s[nt][3] * 0.125f - slope * (c0 + 1.f);
            if (diag) {
                if (jc > rowg0) s[nt][0] = -1e30f;
                if (jc + 1 > rowg0) s[nt][1] = -1e30f;
                if (jc > rowg1) s[nt][2] = -1e30f;
                if (jc + 1 > rowg1) s[nt][3] = -1e30f;
            }
            mx0 = fmaxf(mx0, fmaxf(s[nt][0], s[nt][1]));
            mx1 = fmaxf(mx1, fmaxf(s[nt][2], s[nt][3]));
        }
        mx0 = fmaxf(mx0, __shfl_xor_sync(0xffffffffu, mx0, 1, 4));
        mx0 = fmaxf(mx0, __shfl_xor_sync(0xffffffffu, mx0, 2, 4));
        mx1 = fmaxf(mx1, __shfl_xor_sync(0xffffffffu, mx1, 1, 4));
        mx1 = fmaxf(mx1, __shfl_xor_sync(0xffffffffu, mx1, 2, 4));
        const float mn0 = fmaxf(m0, mx0), mn1 = fmaxf(m1, mx1);
        const float cr0 = __expf(m0 - mn0), cr1 = __expf(m1 - mn1);
        m0 = mn0;
        m1 = mn1;
        float sum0 = 0.f, sum1 = 0.f;
#pragma unroll
        for (int nt = 0; nt < 16; ++nt) {
            s[nt][0] = __expf(s[nt][0] - mn0);
            s[nt][1] = __expf(s[nt][1] - mn0);
            s[nt][2] = __expf(s[nt][2] - mn1);
            s[nt][3] = __expf(s[nt][3] - mn1);
            sum0 += s[nt][0] + s[nt][1];
            sum1 += s[nt][2] + s[nt][3];
        }
        sum0 += __shfl_xor_sync(0xffffffffu, sum0, 1, 4);
        sum0 += __shfl_xor_sync(0xffffffffu, sum0, 2, 4);
        sum1 += __shfl_xor_sync(0xffffffffu, sum1, 1, 4);
        sum1 += __shfl_xor_sync(0xffffffffu, sum1, 2, 4);
        l0 = l0 * cr0 + sum0;
        l1 = l1 * cr1 + sum1;
#pragma unroll
        for (int nt = 0; nt < 8; ++nt) {
            o[nt][0] *= cr0;
            o[nt][1] *= cr0;
            o[nt][2] *= cr1;
            o[nt][3] *= cr1;
        }

        // ---- O += P V (single fp16 MMA); skip zero P strips on diag ----
#pragma unroll
        for (int k16 = 0; k16 < 8; ++k16) {
            if (diag && k16 > w) continue;  // p == 0 exactly (masked)
            uint32_t ph[4];
            ph[0] = pack_f2h(s[2 * k16][0], s[2 * k16][1]);
            ph[1] = pack_f2h(s[2 * k16][2], s[2 * k16][3]);
            ph[2] = pack_f2h(s[2 * k16 + 1][0], s[2 * k16 + 1][1]);
            ph[3] = pack_f2h(s[2 * k16 + 1][2], s[2 * k16 + 1][3]);
            const int row = k16 * 16 + (q & 1) * 8 + r;
#pragma unroll
            for (int cgp = 0; cgp < 4; ++cgp) {
                const int c = cgp * 2 + (q >> 1);
                uint32_t vh[4];
                ldsm4t(vh, sv + row * 128 + ((c ^ r) << 4));
                mma16816(o[cgp * 2], ph, vh);
                mma16816(o[cgp * 2 + 1], ph, vh + 2);
            }
        }
        __syncthreads();
        buf ^= 1;
    }

    // ---- epilogue: normalize, store single fp16 ----
    const float inv0 = 1.f / l0, inv1 = 1.f / l1;
    const size_t orow0 = (size_t)(qrow_base + w * 16 + g) * DIM + hcol;
    const size_t orow1 = orow0 + (size_t)8 * DIM;
#pragma unroll
    for (int nt = 0; nt < 8; ++nt) {
        const int col = nt * 8 + 2 * t;
        *(uint32_t*)&gOh[orow0 + col] = pack_f2h(o[nt][0] * inv0, o[nt][1] * inv0);
        *(uint32_t*)&gOh[orow1 + col] = pack_f2h(o[nt][2] * inv1, o[nt][3] * inv1);
    }
}

// ---------------------------------------------------------------------------
extern "C" void kernel_launch(void* const* d_in, const int* in_sizes, int n_in,
                              void* d_out, int out_size) {
    const float* X  = (const float*)d_in[0];
    const float* Wq = (const float*)d_in[1];
    const float* bq = (const float*)d_in[2];
    const float* Wk = (const float*)d_in[3];
    const float* bk = (const float*)d_in[4];
    const float* Wv = (const float*)d_in[5];
    const float* Wo = (const float*)d_in[6];
    const float* bo = (const float*)d_in[7];
    float* out = (float*)d_out;

    cudaFuncSetAttribute(qkv_mma, cudaFuncAttributeMaxDynamicSharedMemorySize, GEMM_SMEM);
    cudaFuncSetAttribute(out_mma, cudaFuncAttributeMaxDynamicSharedMemorySize, GEMM_SMEM);
    cudaFuncSetAttribute(attn_mma, cudaFuncAttributeMaxDynamicSharedMemorySize, ATTN_SMEM);

    convert_inputs<<<2048, 256>>>(X, Wq, Wk, Wv, Wo);
    qkv_mma<<<dim3(DIM / 128, MROWS / 128, 3), 256, GEMM_SMEM>>>(bq, bk);
    attn_mma<<<dim3(SEQ / 128, BQ * NH), 256, ATTN_SMEM>>>();
    out_mma<<<dim3(DIM / 128, MROWS / 128, 1), 256, GEMM_SMEM>>>(bo, out);
}

// round 11
// speedup vs baseline: 1.5675x; 1.3659x over previous
#include <cuda_runtime.h>
#include <cuda_fp16.h>
#include <math.h>
#include <stdint.h>

// Problem constants
#define BQ   2
#define SEQ  2048
#define DIM  1024
#define NH   16
#define HDIM 64
#define MROWS (BQ * SEQ)   // 4096

// Scratch: everything single fp16 (calibrated error budget allows it).
__device__ __half gXh[MROWS * DIM];
__device__ __half gWh[4 * DIM * DIM];
__device__ __half gQh[MROWS * DIM];
__device__ __half gKh[MROWS * DIM];
__device__ __half gVh[MROWS * DIM];
__device__ __half gOh[MROWS * DIM];

// ---------------------------------------------------------------------------
// Helpers
// ---------------------------------------------------------------------------
__device__ __forceinline__ uint32_t smem_u32(const void* p) {
    uint32_t a;
    asm("{ .reg .u64 t; cvta.to.shared.u64 t, %1; cvt.u32.u64 %0, t; }"
        : "=r"(a) : "l"(p));
    return a;
}
__device__ __forceinline__ void cp16(uint32_t dst, const void* src) {
    asm volatile("cp.async.cg.shared.global [%0], [%1], 16;"
                 :: "r"(dst), "l"(__cvta_generic_to_global(src)));
}
__device__ __forceinline__ void cp_commit() {
    asm volatile("cp.async.commit_group;" ::: "memory");
}
__device__ __forceinline__ void ldsm4(uint32_t* r, uint32_t addr) {
    asm volatile("ldmatrix.sync.aligned.m8n8.x4.shared.b16 {%0,%1,%2,%3}, [%4];"
                 : "=r"(r[0]), "=r"(r[1]), "=r"(r[2]), "=r"(r[3]) : "r"(addr));
}
__device__ __forceinline__ void ldsm4t(uint32_t* r, uint32_t addr) {
    asm volatile("ldmatrix.sync.aligned.m8n8.x4.trans.shared.b16 {%0,%1,%2,%3}, [%4];"
                 : "=r"(r[0]), "=r"(r[1]), "=r"(r[2]), "=r"(r[3]) : "r"(addr));
}
__device__ __forceinline__ void mma16816(float* c, const uint32_t* a, const uint32_t* b) {
    asm volatile(
        "mma.sync.aligned.m16n8k16.row.col.f32.f16.f16.f32 "
        "{%0,%1,%2,%3}, {%4,%5,%6,%7}, {%8,%9}, {%0,%1,%2,%3};"
        : "+f"(c[0]), "+f"(c[1]), "+f"(c[2]), "+f"(c[3])
        : "r"(a[0]), "r"(a[1]), "r"(a[2]), "r"(a[3]), "r"(b[0]), "r"(b[1]));
}
__device__ __forceinline__ uint32_t pack_f2h(float a, float b) {
    __half2 t = __halves2half2(__float2half_rn(a), __float2half_rn(b));
    return *(uint32_t*)&t;
}

// ---------------------------------------------------------------------------
// Convert fp32 inputs -> single fp16 (X and the 4 weight matrices)
// ---------------------------------------------------------------------------
__global__ __launch_bounds__(256) void convert_inputs(
    const float* __restrict__ X, const float* __restrict__ Wq,
    const float* __restrict__ Wk, const float* __restrict__ Wv,
    const float* __restrict__ Wo) {
    const int XQ = MROWS * DIM / 4;
    const int WQ = DIM * DIM / 4;
    const int total4 = XQ + 4 * WQ;
    for (int i = blockIdx.x * blockDim.x + threadIdx.x; i < total4;
         i += gridDim.x * blockDim.x) {
        const float* src;
        __half* dh;
        if (i < XQ) {
            int e = i * 4;
            src = X + e; dh = gXh + e;
        } else {
            int t = i - XQ;
            int w = t / WQ;
            int off = (t - w * WQ) * 4;
            src = (w == 0) ? Wq + off : (w == 1) ? Wk + off
                  : (w == 2) ? Wv + off : Wo + off;
            dh = gWh + (size_t)w * DIM * DIM + off;
        }
        float4 v = *(const float4*)src;
        ((uint32_t*)dh)[0] = pack_f2h(v.x, v.y);
        ((uint32_t*)dh)[1] = pack_f2h(v.z, v.w);
    }
}

// ---------------------------------------------------------------------------
// Single-term fp16 GEMM: 128x128 CTA tile, K-step 32, 8 warps (64x32 tiles),
// 3-stage cp.async, 2 CTAs/SM. OMODE: 0 = fp32 out (+bias), 3 = fp16 (+bias).
// ---------------------------------------------------------------------------
#define STAGE_BYTES 32768
#define SM_BH 16384
#define GEMM_SMEM (3 * STAGE_BYTES)

__device__ __forceinline__ void gemm_fill(uint32_t sbuf,
                                          const __half* __restrict__ A,
                                          const __half* __restrict__ B,
                                          int row0, int col0, int kt, int tid) {
#pragma unroll
    for (int i = 0; i < 2; ++i) {  // A: 512 16B chunks
        int lin = tid + i * 256;
        int m = lin >> 2, c = lin & 3;
        cp16(sbuf + m * 128 + ((c ^ (m & 7)) << 4),
             A + (size_t)(row0 + m) * DIM + kt + c * 8);
    }
#pragma unroll
    for (int i = 0; i < 2; ++i) {  // B: 512 16B chunks
        int lin = tid + i * 256;
        int k = lin >> 4, c = lin & 15;
        cp16(sbuf + SM_BH + k * 256 + ((c >> 3) << 7) +
                 (((c & 7) ^ (k & 7)) << 4),
             B + (size_t)(kt + k) * DIM + col0 + c * 8);
    }
}

template <int OMODE>
__device__ __forceinline__ void mma_gemm_body(
    const __half* __restrict__ Ag, const __half* __restrict__ Bg,
    const float* __restrict__ bias, float* __restrict__ Yf,
    __half* __restrict__ Yh) {
    extern __shared__ __align__(1024) char smem[];
    const uint32_t sb = smem_u32(smem);
    const int tid = threadIdx.x;
    const int row0 = blockIdx.y * 128, col0 = blockIdx.x * 128;
    const int lane = tid & 31, wid = tid >> 5;
    const int wm = wid & 1, wn = wid >> 1;
    const int q = lane >> 3, r = lane & 7;
    const int arow = (q & 1) * 8 + r;
    const int aq = q >> 1;

    float acc[4][4][4];
#pragma unroll
    for (int mt = 0; mt < 4; ++mt)
#pragma unroll
        for (int nt = 0; nt < 4; ++nt)
#pragma unroll
            for (int e = 0; e < 4; ++e) acc[mt][nt][e] = 0.f;

    gemm_fill(sb, Ag, Bg, row0, col0, 0, tid);
    cp_commit();
    gemm_fill(sb + STAGE_BYTES, Ag, Bg, row0, col0, 32, tid);
    cp_commit();

    for (int s = 0; s < 32; ++s) {
        const int buf = s % 3;
        if (s + 2 < 32) {
            gemm_fill(sb + ((s + 2) % 3) * STAGE_BYTES, Ag, Bg, row0, col0,
                      (s + 2) * 32, tid);
            cp_commit();
            asm volatile("cp.async.wait_group 2;" ::: "memory");
        } else if (s + 1 < 32) {
            asm volatile("cp.async.wait_group 1;" ::: "memory");
        } else {
            asm volatile("cp.async.wait_group 0;" ::: "memory");
        }
        __syncthreads();

        const uint32_t sA = sb + buf * STAGE_BYTES;
        const uint32_t sBh = sA + SM_BH;

#pragma unroll
        for (int k16 = 0; k16 < 2; ++k16) {
            uint32_t bh[8];
            {
                const int krow = k16 * 16 + (q & 1) * 8 + r;
#pragma unroll
                for (int g2 = 0; g2 < 2; ++g2) {
                    int cg = wn * 4 + g2 * 2 + (q >> 1);
                    uint32_t baddr = krow * 256 + ((cg >> 3) << 7) +
                                     (((cg & 7) ^ (krow & 7)) << 4);
                    ldsm4t(&bh[g2 * 4], sBh + baddr);
                }
            }
            uint32_t ah[4][4];
#pragma unroll
            for (int mt = 0; mt < 4; ++mt) {
                int row = wm * 64 + mt * 16 + arow;
                int c1 = k16 * 2 + aq;
                ldsm4(ah[mt], sA + row * 128 + ((c1 ^ r) << 4));
            }
#pragma unroll
            for (int mt = 0; mt < 4; ++mt)
#pragma unroll
                for (int nt = 0; nt < 4; ++nt)
                    mma16816(acc[mt][nt], ah[mt], &bh[(nt >> 1) * 4 + (nt & 1) * 2]);
        }
        __syncthreads();
    }

    const int cg = lane >> 2, ct = lane & 3;
#pragma unroll
    for (int mt = 0; mt < 4; ++mt) {
        int r0 = row0 + wm * 64 + mt * 16 + cg;
#pragma unroll
        for (int nt = 0; nt < 4; ++nt) {
            int col = col0 + wn * 32 + nt * 8 + ct * 2;
            float b0 = bias ? bias[col] : 0.f;
            float b1 = bias ? bias[col + 1] : 0.f;
            float v00 = acc[mt][nt][0] + b0, v01 = acc[mt][nt][1] + b1;
            float v10 = acc[mt][nt][2] + b0, v11 = acc[mt][nt][3] + b1;
            if (OMODE == 0) {
                *(float2*)(Yf + (size_t)r0 * DIM + col) = make_float2(v00, v01);
                *(float2*)(Yf + (size_t)(r0 + 8) * DIM + col) = make_float2(v10, v11);
            } else {
                *(uint32_t*)&Yh[(size_t)r0 * DIM + col] = pack_f2h(v00, v01);
                *(uint32_t*)&Yh[(size_t)(r0 + 8) * DIM + col] = pack_f2h(v10, v11);
            }
        }
    }
}

__global__ __launch_bounds__(256, 2) void qkv_mma(const float* __restrict__ bq,
                                                  const float* __restrict__ bk) {
    const int z = blockIdx.z;
    const __half* B = gWh + (size_t)z * DIM * DIM;
    const float* bias = (z == 0) ? bq : (z == 1) ? bk : nullptr;
    __half* Yh = (z == 0) ? gQh : (z == 1) ? gKh : gVh;
    mma_gemm_body<3>(gXh, B, bias, nullptr, Yh);
}

__global__ __launch_bounds__(256, 2) void out_mma(const float* __restrict__ bo,
                                                  float* __restrict__ out) {
    mma_gemm_body<0>(gOh, gWh + (size_t)3 * DIM * DIM, bo, out, nullptr);
}

// ---------------------------------------------------------------------------
// Flash attention (unchanged from R10). QK^T + PV single fp16 MMA.
// Hard causal (soft mask underflows fp32 exp); ALiBi j-window skip;
// diagonal triangular strip skip. smem: Qh 16KB + 2 stages {Kh,Vh} 32KB.
// ---------------------------------------------------------------------------
#define A_ST0 16384
#define A_STAGE 32768
#define ATTN_SMEM (16384 + 2 * 32768)

__global__ __launch_bounds__(256, 1) void attn_mma() {
    extern __shared__ __align__(1024) char smem[];
    const uint32_t sb = smem_u32(smem);
    const int tid = threadIdx.x;
    const int lane = tid & 31, w = tid >> 5;
    const int q = lane >> 3, r = lane & 7;
    const int g = lane >> 2, t = lane & 3;
    const int it = 15 - (int)blockIdx.x;  // heavy tiles first
    const int bh = blockIdx.y;
    const int b = bh >> 4, h = bh & 15;
    const int i0 = it * 128;
    const float slope = exp2f(-0.5f * (float)(h + 1));
    const int qrow_base = b * SEQ + i0;
    const int hcol = h * HDIM;

    // ALiBi window (bit-exact: skipped weights underflow fp32 exp)
    const int Jt_cap = min(16, (int)(100.f / slope) / 128 + 1);
    const int Jt = min(it + 1, Jt_cap);

#pragma unroll
    for (int i = 0; i < 4; ++i) {
        int lin = tid + i * 256;
        int m = lin >> 3, c = lin & 7;
        cp16(sb + m * 128 + ((c ^ (m & 7)) << 4),
             gQh + (size_t)(qrow_base + m) * DIM + hcol + c * 8);
    }
    {
        const int krow_base = b * SEQ;
#pragma unroll
        for (int i = 0; i < 8; ++i) {
            int lin = tid + i * 256;
            int tz = lin >> 10;
            int rem = lin & 1023;
            int m = rem >> 3, c = rem & 7;
            const __half* src = (tz ? gVh : gKh) +
                                (size_t)(krow_base + m) * DIM + hcol + c * 8;
            cp16(sb + A_ST0 + tz * 16384 + m * 128 + ((c ^ (m & 7)) << 4), src);
        }
    }
    cp_commit();

    float o[8][4];
#pragma unroll
    for (int nt = 0; nt < 8; ++nt)
#pragma unroll
        for (int e = 0; e < 4; ++e) o[nt][e] = 0.f;
    float m0 = -1e30f, m1 = -1e30f, l0 = 0.f, l1 = 0.f;
    uint32_t qh[4][4];

    int buf = 0;
    for (int jt = 0; jt < Jt; ++jt) {
        if (jt + 1 < Jt) {
            const int krow_base = b * SEQ + (jt + 1) * 128;
            const uint32_t st = sb + A_ST0 + (buf ^ 1) * A_STAGE;
#pragma unroll
            for (int i = 0; i < 8; ++i) {
                int lin = tid + i * 256;
                int tz = lin >> 10;
                int rem = lin & 1023;
                int m = rem >> 3, c = rem & 7;
                const __half* src = (tz ? gVh : gKh) +
                                    (size_t)(krow_base + m) * DIM + hcol + c * 8;
                cp16(st + tz * 16384 + m * 128 + ((c ^ (m & 7)) << 4), src);
            }
            cp_commit();
            asm volatile("cp.async.wait_group 1;" ::: "memory");
        } else {
            asm volatile("cp.async.wait_group 0;" ::: "memory");
        }
        __syncthreads();

        if (jt == 0) {  // hoist Q fragments
#pragma unroll
            for (int k16 = 0; k16 < 4; ++k16) {
                int row = w * 16 + (q & 1) * 8 + r;
                int c = k16 * 2 + (q >> 1);
                ldsm4(qh[k16], sb + row * 128 + ((c ^ r) << 4));
            }
        }

        const uint32_t sk = sb + A_ST0 + buf * A_STAGE;
        const uint32_t sv = sk + 16384;
        const bool diag = (jt == it);

        float s[16][4];
#pragma unroll
        for (int nt16 = 0; nt16 < 8; ++nt16) {
            if (diag && nt16 > w) {
#pragma unroll
                for (int e = 0; e < 4; ++e) {
                    s[2 * nt16][e] = 0.f;
                    s[2 * nt16 + 1][e] = 0.f;
                }
                continue;
            }
#pragma unroll
            for (int e = 0; e < 4; ++e) {
                s[2 * nt16][e] = 0.f;
                s[2 * nt16 + 1][e] = 0.f;
            }
            const int row = nt16 * 16 + (q >> 1) * 8 + r;
#pragma unroll
            for (int k16 = 0; k16 < 4; ++k16) {
                const int c = k16 * 2 + (q & 1);
                uint32_t kh[4];
                ldsm4(kh, sk + row * 128 + ((c ^ r) << 4));
                mma16816(s[2 * nt16], qh[k16], kh);
                mma16816(s[2 * nt16 + 1], qh[k16], kh + 2);
            }
        }

        const int j0 = jt * 128;
        const int rowg0 = i0 + w * 16 + g;
        const int rowg1 = rowg0 + 8;
        float mx0 = -1e30f, mx1 = -1e30f;
#pragma unroll
        for (int nt = 0; nt < 16; ++nt) {
            const int jc = j0 + nt * 8 + 2 * t;
            const float c0 = (float)jc;
            s[nt][0] = s[nt][0] * 0.125f - slope * c0;
            s[nt][1] = s[nt][1] * 0.125f - slope * (c0 + 1.f);
            s[nt][2] = s[nt][2] * 0.125f - slope * c0;
            s[nt][3] = s[nt][3] * 0.125f - slope * (c0 + 1.f);
            if (diag) {
                if (jc > rowg0) s[nt][0] = -1e30f;
                if (jc + 1 > rowg0) s[nt][1] = -1e30f;
                if (jc > rowg1) s[nt][2] = -1e30f;
                if (jc + 1 > rowg1) s[nt][3] = -1e30f;
            }
            mx0 = fmaxf(mx0, fmaxf(s[nt][0], s[nt][1]));
            mx1 = fmaxf(mx1, fmaxf(s[nt][2], s[nt][3]));
        }
        mx0 = fmaxf(mx0, __shfl_xor_sync(0xffffffffu, mx0, 1, 4));
        mx0 = fmaxf(mx0, __shfl_xor_sync(0xffffffffu, mx0, 2, 4));
        mx1 = fmaxf(mx1, __shfl_xor_sync(0xffffffffu, mx1, 1, 4));
        mx1 = fmaxf(mx1, __shfl_xor_sync(0xffffffffu, mx1, 2, 4));
        const float mn0 = fmaxf(m0, mx0), mn1 = fmaxf(m1, mx1);
        const float cr0 = __expf(m0 - mn0), cr1 = __expf(m1 - mn1);
        m0 = mn0;
        m1 = mn1;
        float sum0 = 0.f, sum1 = 0.f;
#pragma unroll
        for (int nt = 0; nt < 16; ++nt) {
            s[nt][0] = __expf(s[nt][0] - mn0);
            s[nt][1] = __expf(s[nt][1] - mn0);
            s[nt][2] = __expf(s[nt][2] - mn1);
            s[nt][3] = __expf(s[nt][3] - mn1);
            sum0 += s[nt][0] + s[nt][1];
            sum1 += s[nt][2] + s[nt][3];
        }
        sum0 += __shfl_xor_sync(0xffffffffu, sum0, 1, 4);
        sum0 += __shfl_xor_sync(0xffffffffu, sum0, 2, 4);
        sum1 += __shfl_xor_sync(0xffffffffu, sum1, 1, 4);
        sum1 += __shfl_xor_sync(0xffffffffu, sum1, 2, 4);
        l0 = l0 * cr0 + sum0;
        l1 = l1 * cr1 + sum1;
#pragma unroll
        for (int nt = 0; nt < 8; ++nt) {
            o[nt][0] *= cr0;
            o[nt][1] *= cr0;
            o[nt][2] *= cr1;
            o[nt][3] *= cr1;
        }

#pragma unroll
        for (int k16 = 0; k16 < 8; ++k16) {
            if (diag && k16 > w) continue;  // p == 0 exactly (masked)
            uint32_t ph[4];
            ph[0] = pack_f2h(s[2 * k16][0], s[2 * k16][1]);
            ph[1] = pack_f2h(s[2 * k16][2], s[2 * k16][3]);
            ph[2] = pack_f2h(s[2 * k16 + 1][0], s[2 * k16 + 1][1]);
            ph[3] = pack_f2h(s[2 * k16 + 1][2], s[2 * k16 + 1][3]);
            const int row = k16 * 16 + (q & 1) * 8 + r;
#pragma unroll
            for (int cgp = 0; cgp < 4; ++cgp) {
                const int c = cgp * 2 + (q >> 1);
                uint32_t vh[4];
                ldsm4t(vh, sv + row * 128 + ((c ^ r) << 4));
                mma16816(o[cgp * 2], ph, vh);
                mma16816(o[cgp * 2 + 1], ph, vh + 2);
            }
        }
        __syncthreads();
        buf ^= 1;
    }

    const float inv0 = 1.f / l0, inv1 = 1.f / l1;
    const size_t orow0 = (size_t)(qrow_base + w * 16 + g) * DIM + hcol;
    const size_t orow1 = orow0 + (size_t)8 * DIM;
#pragma unroll
    for (int nt = 0; nt < 8; ++nt) {
        const int col = nt * 8 + 2 * t;
        *(uint32_t*)&gOh[orow0 + col] = pack_f2h(o[nt][0] * inv0, o[nt][1] * inv0);
        *(uint32_t*)&gOh[orow1 + col] = pack_f2h(o[nt][2] * inv1, o[nt][3] * inv1);
    }
}

// ---------------------------------------------------------------------------
extern "C" void kernel_launch(void* const* d_in, const int* in_sizes, int n_in,
                              void* d_out, int out_size) {
    const float* X  = (const float*)d_in[0];
    const float* Wq = (const float*)d_in[1];
    const float* bq = (const float*)d_in[2];
    const float* Wk = (const float*)d_in[3];
    const float* bk = (const float*)d_in[4];
    const float* Wv = (const float*)d_in[5];
    const float* Wo = (const float*)d_in[6];
    const float* bo = (const float*)d_in[7];
    float* out = (float*)d_out;

    cudaFuncSetAttribute(qkv_mma, cudaFuncAttributeMaxDynamicSharedMemorySize, GEMM_SMEM);
    cudaFuncSetAttribute(out_mma, cudaFuncAttributeMaxDynamicSharedMemorySize, GEMM_SMEM);
    cudaFuncSetAttribute(attn_mma, cudaFuncAttributeMaxDynamicSharedMemorySize, ATTN_SMEM);

    convert_inputs<<<2048, 256>>>(X, Wq, Wk, Wv, Wo);
    qkv_mma<<<dim3(DIM / 128, MROWS / 128, 3), 256, GEMM_SMEM>>>(bq, bk);
    attn_mma<<<dim3(SEQ / 128, BQ * NH), 256, ATTN_SMEM>>>();
    out_mma<<<dim3(DIM / 128, MROWS / 128, 1), 256, GEMM_SMEM>>>(bo, out);
}

// round 12
// speedup vs baseline: 1.7449x; 1.1132x over previous
#include <cuda_runtime.h>
#include <cuda_fp16.h>
#include <math.h>
#include <stdint.h>

// Problem constants
#define BQ   2
#define SEQ  2048
#define DIM  1024
#define NH   16
#define HDIM 64
#define MROWS (BQ * SEQ)   // 4096

// Scratch: everything single fp16 (calibrated error budget allows it).
__device__ __half gXh[MROWS * DIM];
__device__ __half gWh[4 * DIM * DIM];
__device__ __half gQh[MROWS * DIM];
__device__ __half gKh[MROWS * DIM];
__device__ __half gVh[MROWS * DIM];
__device__ __half gOh[MROWS * DIM];

// ---------------------------------------------------------------------------
// Helpers
// ---------------------------------------------------------------------------
__device__ __forceinline__ uint32_t smem_u32(const void* p) {
    uint32_t a;
    asm("{ .reg .u64 t; cvta.to.shared.u64 t, %1; cvt.u32.u64 %0, t; }"
        : "=r"(a) : "l"(p));
    return a;
}
__device__ __forceinline__ void cp16(uint32_t dst, const void* src) {
    asm volatile("cp.async.cg.shared.global [%0], [%1], 16;"
                 :: "r"(dst), "l"(__cvta_generic_to_global(src)));
}
__device__ __forceinline__ void cp_commit() {
    asm volatile("cp.async.commit_group;" ::: "memory");
}
__device__ __forceinline__ void ldsm4(uint32_t* r, uint32_t addr) {
    asm volatile("ldmatrix.sync.aligned.m8n8.x4.shared.b16 {%0,%1,%2,%3}, [%4];"
                 : "=r"(r[0]), "=r"(r[1]), "=r"(r[2]), "=r"(r[3]) : "r"(addr));
}
__device__ __forceinline__ void ldsm4t(uint32_t* r, uint32_t addr) {
    asm volatile("ldmatrix.sync.aligned.m8n8.x4.trans.shared.b16 {%0,%1,%2,%3}, [%4];"
                 : "=r"(r[0]), "=r"(r[1]), "=r"(r[2]), "=r"(r[3]) : "r"(addr));
}
__device__ __forceinline__ void mma16816(float* c, const uint32_t* a, const uint32_t* b) {
    asm volatile(
        "mma.sync.aligned.m16n8k16.row.col.f32.f16.f16.f32 "
        "{%0,%1,%2,%3}, {%4,%5,%6,%7}, {%8,%9}, {%0,%1,%2,%3};"
        : "+f"(c[0]), "+f"(c[1]), "+f"(c[2]), "+f"(c[3])
        : "r"(a[0]), "r"(a[1]), "r"(a[2]), "r"(a[3]), "r"(b[0]), "r"(b[1]));
}
__device__ __forceinline__ uint32_t pack_f2h(float a, float b) {
    __half2 t = __halves2half2(__float2half_rn(a), __float2half_rn(b));
    return *(uint32_t*)&t;
}

// ---------------------------------------------------------------------------
// Convert fp32 inputs -> single fp16 (X and the 4 weight matrices)
// ---------------------------------------------------------------------------
__global__ __launch_bounds__(256) void convert_inputs(
    const float* __restrict__ X, const float* __restrict__ Wq,
    const float* __restrict__ Wk, const float* __restrict__ Wv,
    const float* __restrict__ Wo) {
    const int XQ = MROWS * DIM / 4;
    const int WQ = DIM * DIM / 4;
    const int total4 = XQ + 4 * WQ;
    for (int i = blockIdx.x * blockDim.x + threadIdx.x; i < total4;
         i += gridDim.x * blockDim.x) {
        const float* src;
        __half* dh;
        if (i < XQ) {
            int e = i * 4;
            src = X + e; dh = gXh + e;
        } else {
            int t = i - XQ;
            int w = t / WQ;
            int off = (t - w * WQ) * 4;
            src = (w == 0) ? Wq + off : (w == 1) ? Wk + off
                  : (w == 2) ? Wv + off : Wo + off;
            dh = gWh + (size_t)w * DIM * DIM + off;
        }
        float4 v = *(const float4*)src;
        ((uint32_t*)dh)[0] = pack_f2h(v.x, v.y);
        ((uint32_t*)dh)[1] = pack_f2h(v.z, v.w);
    }
}

// ---------------------------------------------------------------------------
// Single-term fp16 GEMM (unchanged from R11): 128x128 CTA tile, K-step 32,
// 8 warps (64x32 tiles), 3-stage cp.async, 2 CTAs/SM.
// ---------------------------------------------------------------------------
#define STAGE_BYTES 32768
#define SM_BH 16384
#define GEMM_SMEM (3 * STAGE_BYTES)

__device__ __forceinline__ void gemm_fill(uint32_t sbuf,
                                          const __half* __restrict__ A,
                                          const __half* __restrict__ B,
                                          int row0, int col0, int kt, int tid) {
#pragma unroll
    for (int i = 0; i < 2; ++i) {
        int lin = tid + i * 256;
        int m = lin >> 2, c = lin & 3;
        cp16(sbuf + m * 128 + ((c ^ (m & 7)) << 4),
             A + (size_t)(row0 + m) * DIM + kt + c * 8);
    }
#pragma unroll
    for (int i = 0; i < 2; ++i) {
        int lin = tid + i * 256;
        int k = lin >> 4, c = lin & 15;
        cp16(sbuf + SM_BH + k * 256 + ((c >> 3) << 7) +
                 (((c & 7) ^ (k & 7)) << 4),
             B + (size_t)(kt + k) * DIM + col0 + c * 8);
    }
}

template <int OMODE>
__device__ __forceinline__ void mma_gemm_body(
    const __half* __restrict__ Ag, const __half* __restrict__ Bg,
    const float* __restrict__ bias, float* __restrict__ Yf,
    __half* __restrict__ Yh) {
    extern __shared__ __align__(1024) char smem[];
    const uint32_t sb = smem_u32(smem);
    const int tid = threadIdx.x;
    const int row0 = blockIdx.y * 128, col0 = blockIdx.x * 128;
    const int lane = tid & 31, wid = tid >> 5;
    const int wm = wid & 1, wn = wid >> 1;
    const int q = lane >> 3, r = lane & 7;
    const int arow = (q & 1) * 8 + r;
    const int aq = q >> 1;

    float acc[4][4][4];
#pragma unroll
    for (int mt = 0; mt < 4; ++mt)
#pragma unroll
        for (int nt = 0; nt < 4; ++nt)
#pragma unroll
            for (int e = 0; e < 4; ++e) acc[mt][nt][e] = 0.f;

    gemm_fill(sb, Ag, Bg, row0, col0, 0, tid);
    cp_commit();
    gemm_fill(sb + STAGE_BYTES, Ag, Bg, row0, col0, 32, tid);
    cp_commit();

    for (int s = 0; s < 32; ++s) {
        const int buf = s % 3;
        if (s + 2 < 32) {
            gemm_fill(sb + ((s + 2) % 3) * STAGE_BYTES, Ag, Bg, row0, col0,
                      (s + 2) * 32, tid);
            cp_commit();
            asm volatile("cp.async.wait_group 2;" ::: "memory");
        } else if (s + 1 < 32) {
            asm volatile("cp.async.wait_group 1;" ::: "memory");
        } else {
            asm volatile("cp.async.wait_group 0;" ::: "memory");
        }
        __syncthreads();

        const uint32_t sA = sb + buf * STAGE_BYTES;
        const uint32_t sBh = sA + SM_BH;

#pragma unroll
        for (int k16 = 0; k16 < 2; ++k16) {
            uint32_t bh[8];
            {
                const int krow = k16 * 16 + (q & 1) * 8 + r;
#pragma unroll
                for (int g2 = 0; g2 < 2; ++g2) {
                    int cg = wn * 4 + g2 * 2 + (q >> 1);
                    uint32_t baddr = krow * 256 + ((cg >> 3) << 7) +
                                     (((cg & 7) ^ (krow & 7)) << 4);
                    ldsm4t(&bh[g2 * 4], sBh + baddr);
                }
            }
            uint32_t ah[4][4];
#pragma unroll
            for (int mt = 0; mt < 4; ++mt) {
                int row = wm * 64 + mt * 16 + arow;
                int c1 = k16 * 2 + aq;
                ldsm4(ah[mt], sA + row * 128 + ((c1 ^ r) << 4));
            }
#pragma unroll
            for (int mt = 0; mt < 4; ++mt)
#pragma unroll
                for (int nt = 0; nt < 4; ++nt)
                    mma16816(acc[mt][nt], ah[mt], &bh[(nt >> 1) * 4 + (nt & 1) * 2]);
        }
        __syncthreads();
    }

    const int cg = lane >> 2, ct = lane & 3;
#pragma unroll
    for (int mt = 0; mt < 4; ++mt) {
        int r0 = row0 + wm * 64 + mt * 16 + cg;
#pragma unroll
        for (int nt = 0; nt < 4; ++nt) {
            int col = col0 + wn * 32 + nt * 8 + ct * 2;
            float b0 = bias ? bias[col] : 0.f;
            float b1 = bias ? bias[col + 1] : 0.f;
            float v00 = acc[mt][nt][0] + b0, v01 = acc[mt][nt][1] + b1;
            float v10 = acc[mt][nt][2] + b0, v11 = acc[mt][nt][3] + b1;
            if (OMODE == 0) {
                *(float2*)(Yf + (size_t)r0 * DIM + col) = make_float2(v00, v01);
                *(float2*)(Yf + (size_t)(r0 + 8) * DIM + col) = make_float2(v10, v11);
            } else {
                *(uint32_t*)&Yh[(size_t)r0 * DIM + col] = pack_f2h(v00, v01);
                *(uint32_t*)&Yh[(size_t)(r0 + 8) * DIM + col] = pack_f2h(v10, v11);
            }
        }
    }
}

__global__ __launch_bounds__(256, 2) void qkv_mma(const float* __restrict__ bq,
                                                  const float* __restrict__ bk) {
    const int z = blockIdx.z;
    const __half* B = gWh + (size_t)z * DIM * DIM;
    const float* bias = (z == 0) ? bq : (z == 1) ? bk : nullptr;
    __half* Yh = (z == 0) ? gQh : (z == 1) ? gKh : gVh;
    mma_gemm_body<3>(gXh, B, bias, nullptr, Yh);
}

__global__ __launch_bounds__(256, 2) void out_mma(const float* __restrict__ bo,
                                                  float* __restrict__ out) {
    mma_gemm_body<0>(gOh, gWh + (size_t)3 * DIM * DIM, bo, out, nullptr);
}

// ---------------------------------------------------------------------------
// Flash attention, j-tile = 64 keys, 2 CTAs/SM.
// 8 warps; warp w owns 16 query rows of a 128-row i-tile.
// Hard causal (soft mask underflows fp32 exp); ALiBi window at 64-key
// granularity; per-warp strip skips; element mask gated by maskzone.
// smem: Qh 16KB + 2 stages of {Kh 8KB, Vh 8KB} = 48KB.
// ---------------------------------------------------------------------------
#define A_ST0 16384
#define A_STAGE 16384
#define ATTN_SMEM (16384 + 2 * 16384)

__global__ __launch_bounds__(256, 2) void attn_mma() {
    extern __shared__ __align__(1024) char smem[];
    const uint32_t sb = smem_u32(smem);
    const int tid = threadIdx.x;
    const int lane = tid & 31, w = tid >> 5;
    const int q = lane >> 3, r = lane & 7;
    const int g = lane >> 2, t = lane & 3;
    const int it = 15 - (int)blockIdx.x;     // heavy i-tiles first
    const int y = blockIdx.y;
    const int b = y & 1;
    const int h = 15 - (y >> 1);             // heavy heads first
    const int i0 = it * 128;
    const float slope = exp2f(-0.5f * (float)(h + 1));
    const int qrow_base = b * SEQ + i0;
    const int hcol = h * HDIM;

    // ALiBi window in 64-key tiles (bit-exact: skipped weights underflow)
    const int Jt_cap = min(32, (int)(100.f / slope) / 64 + 1);
    const int Jt = min(2 * it + 2, Jt_cap);

    // ---- fill Q (16KB) ----
#pragma unroll
    for (int i = 0; i < 4; ++i) {
        int lin = tid + i * 256;
        int m = lin >> 3, c = lin & 7;
        cp16(sb + m * 128 + ((c ^ (m & 7)) << 4),
             gQh + (size_t)(qrow_base + m) * DIM + hcol + c * 8);
    }
    // ---- fill K/V stage 0 (16KB: K 8KB + V 8KB, 64 rows each) ----
    {
        const int krow_base = b * SEQ;
#pragma unroll
        for (int i = 0; i < 4; ++i) {
            int lin = tid + i * 256;
            int tz = lin >> 9;            // 0=Kh 1=Vh
            int rem = lin & 511;
            int m = rem >> 3, c = rem & 7;
            const __half* src = (tz ? gVh : gKh) +
                                (size_t)(krow_base + m) * DIM + hcol + c * 8;
            cp16(sb + A_ST0 + tz * 8192 + m * 128 + ((c ^ (m & 7)) << 4), src);
        }
    }
    cp_commit();

    float o[8][4];
#pragma unroll
    for (int nt = 0; nt < 8; ++nt)
#pragma unroll
        for (int e = 0; e < 4; ++e) o[nt][e] = 0.f;
    float m0 = -1e30f, m1 = -1e30f, l0 = 0.f, l1 = 0.f;
    uint32_t qh[4][4];

    const int rowlast = i0 + w * 16 + 15;   // warp's last (largest) query row
    int buf = 0;
    for (int jt = 0; jt < Jt; ++jt) {
        if (jt + 1 < Jt) {
            const int krow_base = b * SEQ + (jt + 1) * 64;
            const uint32_t st = sb + A_ST0 + (buf ^ 1) * A_STAGE;
#pragma unroll
            for (int i = 0; i < 4; ++i) {
                int lin = tid + i * 256;
                int tz = lin >> 9;
                int rem = lin & 511;
                int m = rem >> 3, c = rem & 7;
                const __half* src = (tz ? gVh : gKh) +
                                    (size_t)(krow_base + m) * DIM + hcol + c * 8;
                cp16(st + tz * 8192 + m * 128 + ((c ^ (m & 7)) << 4), src);
            }
            cp_commit();
            asm volatile("cp.async.wait_group 1;" ::: "memory");
        } else {
            asm volatile("cp.async.wait_group 0;" ::: "memory");
        }
        __syncthreads();

        if (jt == 0) {  // hoist Q fragments
#pragma unroll
            for (int k16 = 0; k16 < 4; ++k16) {
                int row = w * 16 + (q & 1) * 8 + r;
                int c = k16 * 2 + (q >> 1);
                ldsm4(qh[k16], sb + row * 128 + ((c ^ r) << 4));
            }
        }

        const uint32_t sk = sb + A_ST0 + buf * A_STAGE;
        const uint32_t sv = sk + 8192;
        const int j0 = jt * 64;
        const bool maskzone = (j0 + 63) > (i0 + w * 16);

        // ---- S = Q K^T over 64 keys (4 strips of 16) ----
        float s[8][4];
#pragma unroll
        for (int nt16 = 0; nt16 < 4; ++nt16) {
#pragma unroll
            for (int e = 0; e < 4; ++e) {
                s[2 * nt16][e] = 0.f;
                s[2 * nt16 + 1][e] = 0.f;
            }
            if (j0 + nt16 * 16 > rowlast) continue;  // fully masked strip
            const int row = nt16 * 16 + (q >> 1) * 8 + r;
#pragma unroll
            for (int k16 = 0; k16 < 4; ++k16) {
                const int c = k16 * 2 + (q & 1);
                uint32_t kh[4];
                ldsm4(kh, sk + row * 128 + ((c ^ r) << 4));
                mma16816(s[2 * nt16], qh[k16], kh);
                mma16816(s[2 * nt16 + 1], qh[k16], kh + 2);
            }
        }

        // ---- online softmax over this 64-key tile ----
        const int rowg0 = i0 + w * 16 + g;
        const int rowg1 = rowg0 + 8;
        float mx0 = -1e30f, mx1 = -1e30f;
#pragma unroll
        for (int nt = 0; nt < 8; ++nt) {
            const int jc = j0 + nt * 8 + 2 * t;
            const float c0 = (float)jc;
            s[nt][0] = s[nt][0] * 0.125f - slope * c0;
            s[nt][1] = s[nt][1] * 0.125f - slope * (c0 + 1.f);
            s[nt][2] = s[nt][2] * 0.125f - slope * c0;
            s[nt][3] = s[nt][3] * 0.125f - slope * (c0 + 1.f);
            if (maskzone) {
                if (jc > rowg0) s[nt][0] = -1e30f;
                if (jc + 1 > rowg0) s[nt][1] = -1e30f;
                if (jc > rowg1) s[nt][2] = -1e30f;
                if (jc + 1 > rowg1) s[nt][3] = -1e30f;
            }
            mx0 = fmaxf(mx0, fmaxf(s[nt][0], s[nt][1]));
            mx1 = fmaxf(mx1, fmaxf(s[nt][2], s[nt][3]));
        }
        mx0 = fmaxf(mx0, __shfl_xor_sync(0xffffffffu, mx0, 1, 4));
        mx0 = fmaxf(mx0, __shfl_xor_sync(0xffffffffu, mx0, 2, 4));
        mx1 = fmaxf(mx1, __shfl_xor_sync(0xffffffffu, mx1, 1, 4));
        mx1 = fmaxf(mx1, __shfl_xor_sync(0xffffffffu, mx1, 2, 4));
        const float mn0 = fmaxf(m0, mx0), mn1 = fmaxf(m1, mx1);
        const float cr0 = __expf(m0 - mn0), cr1 = __expf(m1 - mn1);
        m0 = mn0;
        m1 = mn1;
        float sum0 = 0.f, sum1 = 0.f;
#pragma unroll
        for (int nt = 0; nt < 8; ++nt) {
            s[nt][0] = __expf(s[nt][0] - mn0);
            s[nt][1] = __expf(s[nt][1] - mn0);
            s[nt][2] = __expf(s[nt][2] - mn1);
            s[nt][3] = __expf(s[nt][3] - mn1);
            sum0 += s[nt][0] + s[nt][1];
            sum1 += s[nt][2] + s[nt][3];
        }
        sum0 += __shfl_xor_sync(0xffffffffu, sum0, 1, 4);
        sum0 += __shfl_xor_sync(0xffffffffu, sum0, 2, 4);
        sum1 += __shfl_xor_sync(0xffffffffu, sum1, 1, 4);
        sum1 += __shfl_xor_sync(0xffffffffu, sum1, 2, 4);
        l0 = l0 * cr0 + sum0;
        l1 = l1 * cr1 + sum1;
#pragma unroll
        for (int nt = 0; nt < 8; ++nt) {
            o[nt][0] *= cr0;
            o[nt][1] *= cr0;
            o[nt][2] *= cr1;
            o[nt][3] *= cr1;
        }

        // ---- O += P V over 64 keys (4 k16 strips) ----
#pragma unroll
        for (int k16 = 0; k16 < 4; ++k16) {
            if (j0 + k16 * 16 > rowlast) continue;  // P strip exactly zero
            uint32_t ph[4];
            ph[0] = pack_f2h(s[2 * k16][0], s[2 * k16][1]);
            ph[1] = pack_f2h(s[2 * k16][2], s[2 * k16][3]);
            ph[2] = pack_f2h(s[2 * k16 + 1][0], s[2 * k16 + 1][1]);
            ph[3] = pack_f2h(s[2 * k16 + 1][2], s[2 * k16 + 1][3]);
            const int row = k16 * 16 + (q & 1) * 8 + r;
#pragma unroll
            for (int cgp = 0; cgp < 4; ++cgp) {
                const int c = cgp * 2 + (q >> 1);
                uint32_t vh[4];
                ldsm4t(vh, sv + row * 128 + ((c ^ r) << 4));
                mma16816(o[cgp * 2], ph, vh);
                mma16816(o[cgp * 2 + 1], ph, vh + 2);
            }
        }
        __syncthreads();
        buf ^= 1;
    }

    // ---- epilogue: normalize, store single fp16 ----
    const float inv0 = 1.f / l0, inv1 = 1.f / l1;
    const size_t orow0 = (size_t)(qrow_base + w * 16 + g) * DIM + hcol;
    const size_t orow1 = orow0 + (size_t)8 * DIM;
#pragma unroll
    for (int nt = 0; nt < 8; ++nt) {
        const int col = nt * 8 + 2 * t;
        *(uint32_t*)&gOh[orow0 + col] = pack_f2h(o[nt][0] * inv0, o[nt][1] * inv0);
        *(uint32_t*)&gOh[orow1 + col] = pack_f2h(o[nt][2] * inv1, o[nt][3] * inv1);
    }
}

// ---------------------------------------------------------------------------
extern "C" void kernel_launch(void* const* d_in, const int* in_sizes, int n_in,
                              void* d_out, int out_size) {
    const float* X  = (const float*)d_in[0];
    const float* Wq = (const float*)d_in[1];
    const float* bq = (const float*)d_in[2];
    const float* Wk = (const float*)d_in[3];
    const float* bk = (const float*)d_in[4];
    const float* Wv = (const float*)d_in[5];
    const float* Wo = (const float*)d_in[6];
    const float* bo = (const float*)d_in[7];
    float* out = (float*)d_out;

    cudaFuncSetAttribute(qkv_mma, cudaFuncAttributeMaxDynamicSharedMemorySize, GEMM_SMEM);
    cudaFuncSetAttribute(out_mma, cudaFuncAttributeMaxDynamicSharedMemorySize, GEMM_SMEM);
    cudaFuncSetAttribute(attn_mma, cudaFuncAttributeMaxDynamicSharedMemorySize, ATTN_SMEM);

    convert_inputs<<<2048, 256>>>(X, Wq, Wk, Wv, Wo);
    qkv_mma<<<dim3(DIM / 128, MROWS / 128, 3), 256, GEMM_SMEM>>>(bq, bk);
    attn_mma<<<dim3(SEQ / 128, BQ * NH), 256, ATTN_SMEM>>>();
    out_mma<<<dim3(DIM / 128, MROWS / 128, 1), 256, GEMM_SMEM>>>(bo, out);
}

// round 13
// speedup vs baseline: 1.7962x; 1.0294x over previous
#include <cuda_runtime.h>
#include <cuda_fp16.h>
#include <math.h>
#include <stdint.h>

// Problem constants
#define BQ   2
#define SEQ  2048
#define DIM  1024
#define NH   16
#define HDIM 64
#define MROWS (BQ * SEQ)   // 4096

// Scratch: everything single fp16 (calibrated error budget allows it).
__device__ __half gXh[MROWS * DIM];
__device__ __half gWh[4 * DIM * DIM];
__device__ __half gQh[MROWS * DIM];
__device__ __half gKh[MROWS * DIM];
__device__ __half gVh[MROWS * DIM];
__device__ __half gOh[MROWS * DIM];

// ---------------------------------------------------------------------------
// Helpers
// ---------------------------------------------------------------------------
__device__ __forceinline__ uint32_t smem_u32(const void* p) {
    uint32_t a;
    asm("{ .reg .u64 t; cvta.to.shared.u64 t, %1; cvt.u32.u64 %0, t; }"
        : "=r"(a) : "l"(p));
    return a;
}
__device__ __forceinline__ void cp16(uint32_t dst, const void* src) {
    asm volatile("cp.async.cg.shared.global [%0], [%1], 16;"
                 :: "r"(dst), "l"(__cvta_generic_to_global(src)));
}
__device__ __forceinline__ void cp_commit() {
    asm volatile("cp.async.commit_group;" ::: "memory");
}
__device__ __forceinline__ void ldsm4(uint32_t* r, uint32_t addr) {
    asm volatile("ldmatrix.sync.aligned.m8n8.x4.shared.b16 {%0,%1,%2,%3}, [%4];"
                 : "=r"(r[0]), "=r"(r[1]), "=r"(r[2]), "=r"(r[3]) : "r"(addr));
}
__device__ __forceinline__ void ldsm4t(uint32_t* r, uint32_t addr) {
    asm volatile("ldmatrix.sync.aligned.m8n8.x4.trans.shared.b16 {%0,%1,%2,%3}, [%4];"
                 : "=r"(r[0]), "=r"(r[1]), "=r"(r[2]), "=r"(r[3]) : "r"(addr));
}
__device__ __forceinline__ void mma16816(float* c, const uint32_t* a, const uint32_t* b) {
    asm volatile(
        "mma.sync.aligned.m16n8k16.row.col.f32.f16.f16.f32 "
        "{%0,%1,%2,%3}, {%4,%5,%6,%7}, {%8,%9}, {%0,%1,%2,%3};"
        : "+f"(c[0]), "+f"(c[1]), "+f"(c[2]), "+f"(c[3])
        : "r"(a[0]), "r"(a[1]), "r"(a[2]), "r"(a[3]), "r"(b[0]), "r"(b[1]));
}
__device__ __forceinline__ uint32_t pack_f2h(float a, float b) {
    __half2 t = __halves2half2(__float2half_rn(a), __float2half_rn(b));
    return *(uint32_t*)&t;
}

// ---------------------------------------------------------------------------
// Convert fp32 inputs -> single fp16 (X and the 4 weight matrices)
// ---------------------------------------------------------------------------
__global__ __launch_bounds__(256) void convert_inputs(
    const float* __restrict__ X, const float* __restrict__ Wq,
    const float* __restrict__ Wk, const float* __restrict__ Wv,
    const float* __restrict__ Wo) {
    const int XQ = MROWS * DIM / 4;
    const int WQ = DIM * DIM / 4;
    const int total4 = XQ + 4 * WQ;
    for (int i = blockIdx.x * blockDim.x + threadIdx.x; i < total4;
         i += gridDim.x * blockDim.x) {
        const float* src;
        __half* dh;
        if (i < XQ) {
            int e = i * 4;
            src = X + e; dh = gXh + e;
        } else {
            int t = i - XQ;
            int w = t / WQ;
            int off = (t - w * WQ) * 4;
            src = (w == 0) ? Wq + off : (w == 1) ? Wk + off
                  : (w == 2) ? Wv + off : Wo + off;
            dh = gWh + (size_t)w * DIM * DIM + off;
        }
        float4 v = *(const float4*)src;
        ((uint32_t*)dh)[0] = pack_f2h(v.x, v.y);
        ((uint32_t*)dh)[1] = pack_f2h(v.z, v.w);
    }
}

// ---------------------------------------------------------------------------
// Single-term fp16 GEMM: 128x128 CTA tile, K-step 64, 8 warps (64x32 tiles),
// 2-stage cp.async (32KB/stage: A 128x128B fully used + B 64x256B), 2 CTAs/SM.
// OMODE: 0 = fp32 out (+bias), 3 = fp16 out (+bias).
// ---------------------------------------------------------------------------
#define STAGE_BYTES 32768
#define SM_BH 16384
#define GEMM_SMEM (2 * STAGE_BYTES)

__device__ __forceinline__ void gemm_fill(uint32_t sbuf,
                                          const __half* __restrict__ A,
                                          const __half* __restrict__ B,
                                          int row0, int col0, int kt, int tid) {
#pragma unroll
    for (int i = 0; i < 4; ++i) {  // A: 128 rows x 128B (64 k values)
        int lin = tid + i * 256;
        int m = lin >> 3, c = lin & 7;
        cp16(sbuf + m * 128 + ((c ^ (m & 7)) << 4),
             A + (size_t)(row0 + m) * DIM + kt + c * 8);
    }
#pragma unroll
    for (int i = 0; i < 4; ++i) {  // B: 64 k-rows x 256B
        int lin = tid + i * 256;
        int k = lin >> 4, c = lin & 15;
        cp16(sbuf + SM_BH + k * 256 + ((c >> 3) << 7) +
                 (((c & 7) ^ (k & 7)) << 4),
             B + (size_t)(kt + k) * DIM + col0 + c * 8);
    }
}

template <int OMODE>
__device__ __forceinline__ void mma_gemm_body(
    const __half* __restrict__ Ag, const __half* __restrict__ Bg,
    const float* __restrict__ bias, float* __restrict__ Yf,
    __half* __restrict__ Yh) {
    extern __shared__ __align__(1024) char smem[];
    const uint32_t sb = smem_u32(smem);
    const int tid = threadIdx.x;
    const int row0 = blockIdx.y * 128, col0 = blockIdx.x * 128;
    const int lane = tid & 31, wid = tid >> 5;
    const int wm = wid & 1, wn = wid >> 1;
    const int q = lane >> 3, r = lane & 7;
    const int arow = (q & 1) * 8 + r;
    const int aq = q >> 1;

    float acc[4][4][4];
#pragma unroll
    for (int mt = 0; mt < 4; ++mt)
#pragma unroll
        for (int nt = 0; nt < 4; ++nt)
#pragma unroll
            for (int e = 0; e < 4; ++e) acc[mt][nt][e] = 0.f;

    gemm_fill(sb, Ag, Bg, row0, col0, 0, tid);
    cp_commit();

    for (int s = 0; s < 16; ++s) {  // 16 steps of K=64
        const int buf = s & 1;
        if (s + 1 < 16) {
            gemm_fill(sb + (buf ^ 1) * STAGE_BYTES, Ag, Bg, row0, col0,
                      (s + 1) * 64, tid);
            cp_commit();
            asm volatile("cp.async.wait_group 1;" ::: "memory");
        } else {
            asm volatile("cp.async.wait_group 0;" ::: "memory");
        }
        __syncthreads();

        const uint32_t sA = sb + buf * STAGE_BYTES;
        const uint32_t sBh = sA + SM_BH;

#pragma unroll
        for (int k16 = 0; k16 < 4; ++k16) {
            uint32_t bh[8];
            {
                const int krow = k16 * 16 + (q & 1) * 8 + r;
#pragma unroll
                for (int g2 = 0; g2 < 2; ++g2) {
                    int cg = wn * 4 + g2 * 2 + (q >> 1);
                    uint32_t baddr = krow * 256 + ((cg >> 3) << 7) +
                                     (((cg & 7) ^ (krow & 7)) << 4);
                    ldsm4t(&bh[g2 * 4], sBh + baddr);
                }
            }
            uint32_t ah[4][4];
#pragma unroll
            for (int mt = 0; mt < 4; ++mt) {
                int row = wm * 64 + mt * 16 + arow;
                int c1 = k16 * 2 + aq;
                ldsm4(ah[mt], sA + row * 128 + ((c1 ^ r) << 4));
            }
#pragma unroll
            for (int mt = 0; mt < 4; ++mt)
#pragma unroll
                for (int nt = 0; nt < 4; ++nt)
                    mma16816(acc[mt][nt], ah[mt], &bh[(nt >> 1) * 4 + (nt & 1) * 2]);
        }
        __syncthreads();
    }

    const int cg = lane >> 2, ct = lane & 3;
#pragma unroll
    for (int mt = 0; mt < 4; ++mt) {
        int r0 = row0 + wm * 64 + mt * 16 + cg;
#pragma unroll
        for (int nt = 0; nt < 4; ++nt) {
            int col = col0 + wn * 32 + nt * 8 + ct * 2;
            float b0 = bias ? bias[col] : 0.f;
            float b1 = bias ? bias[col + 1] : 0.f;
            float v00 = acc[mt][nt][0] + b0, v01 = acc[mt][nt][1] + b1;
            float v10 = acc[mt][nt][2] + b0, v11 = acc[mt][nt][3] + b1;
            if (OMODE == 0) {
                *(float2*)(Yf + (size_t)r0 * DIM + col) = make_float2(v00, v01);
                *(float2*)(Yf + (size_t)(r0 + 8) * DIM + col) = make_float2(v10, v11);
            } else {
                *(uint32_t*)&Yh[(size_t)r0 * DIM + col] = pack_f2h(v00, v01);
                *(uint32_t*)&Yh[(size_t)(r0 + 8) * DIM + col] = pack_f2h(v10, v11);
            }
        }
    }
}

__global__ __launch_bounds__(256, 2) void qkv_mma(const float* __restrict__ bq,
                                                  const float* __restrict__ bk) {
    const int z = blockIdx.z;
    const __half* B = gWh + (size_t)z * DIM * DIM;
    const float* bias = (z == 0) ? bq : (z == 1) ? bk : nullptr;
    __half* Yh = (z == 0) ? gQh : (z == 1) ? gKh : gVh;
    mma_gemm_body<3>(gXh, B, bias, nullptr, Yh);
}

__global__ __launch_bounds__(256, 2) void out_mma(const float* __restrict__ bo,
                                                  float* __restrict__ out) {
    mma_gemm_body<0>(gOh, gWh + (size_t)3 * DIM * DIM, bo, out, nullptr);
}

// ---------------------------------------------------------------------------
// Flash attention, j-tile = 64 keys, 3-stage K/V pipeline, 2 CTAs/SM.
// 8 warps; warp w owns 16 query rows of a 128-row i-tile.
// Hard causal (soft mask underflows fp32 exp); ALiBi window at 64-key
// granularity; per-warp strip skips. smem: Q 16KB + 3 stages x 16KB = 64KB.
// ---------------------------------------------------------------------------
#define A_ST0 16384
#define A_STAGE 16384
#define ATTN_SMEM (16384 + 3 * 16384)

__device__ __forceinline__ void attn_fill_kv(uint32_t st, int krow_base,
                                             int hcol, int tid) {
#pragma unroll
    for (int i = 0; i < 4; ++i) {
        int lin = tid + i * 256;
        int tz = lin >> 9;            // 0=Kh 1=Vh
        int rem = lin & 511;
        int m = rem >> 3, c = rem & 7;
        const __half* src = (tz ? gVh : gKh) +
                            (size_t)(krow_base + m) * DIM + hcol + c * 8;
        cp16(st + tz * 8192 + m * 128 + ((c ^ (m & 7)) << 4), src);
    }
}

__global__ __launch_bounds__(256, 2) void attn_mma() {
    extern __shared__ __align__(1024) char smem[];
    const uint32_t sb = smem_u32(smem);
    const int tid = threadIdx.x;
    const int lane = tid & 31, w = tid >> 5;
    const int q = lane >> 3, r = lane & 7;
    const int g = lane >> 2, t = lane & 3;
    const int it = 15 - (int)blockIdx.x;     // heavy i-tiles first
    const int y = blockIdx.y;
    const int b = y & 1;
    const int h = 15 - (y >> 1);             // heavy heads first
    const int i0 = it * 128;
    const float slope = exp2f(-0.5f * (float)(h + 1));
    const int qrow_base = b * SEQ + i0;
    const int hcol = h * HDIM;
    const int kbase = b * SEQ;

    // ALiBi window in 64-key tiles (bit-exact: skipped weights underflow)
    const int Jt_cap = min(32, (int)(100.f / slope) / 64 + 1);
    const int Jt = min(2 * it + 2, Jt_cap);  // Jt >= 2 always

    // ---- fill Q (16KB) + K/V stage 0, one group ----
#pragma unroll
    for (int i = 0; i < 4; ++i) {
        int lin = tid + i * 256;
        int m = lin >> 3, c = lin & 7;
        cp16(sb + m * 128 + ((c ^ (m & 7)) << 4),
             gQh + (size_t)(qrow_base + m) * DIM + hcol + c * 8);
    }
    attn_fill_kv(sb + A_ST0, kbase, hcol, tid);
    cp_commit();
    // ---- K/V stage 1 (Jt >= 2 guaranteed) ----
    attn_fill_kv(sb + A_ST0 + A_STAGE, kbase + 64, hcol, tid);
    cp_commit();

    float o[8][4];
#pragma unroll
    for (int nt = 0; nt < 8; ++nt)
#pragma unroll
        for (int e = 0; e < 4; ++e) o[nt][e] = 0.f;
    float m0 = -1e30f, m1 = -1e30f, l0 = 0.f, l1 = 0.f;
    uint32_t qh[4][4];

    const int rowlast = i0 + w * 16 + 15;   // warp's last (largest) query row
    for (int jt = 0; jt < Jt; ++jt) {
        const int buf = jt % 3;
        if (jt + 2 < Jt) {
            attn_fill_kv(sb + A_ST0 + ((jt + 2) % 3) * A_STAGE,
                         kbase + (jt + 2) * 64, hcol, tid);
            cp_commit();
            asm volatile("cp.async.wait_group 2;" ::: "memory");
        } else if (jt + 1 < Jt) {
            asm volatile("cp.async.wait_group 1;" ::: "memory");
        } else {
            asm volatile("cp.async.wait_group 0;" ::: "memory");
        }
        __syncthreads();

        if (jt == 0) {  // hoist Q fragments
#pragma unroll
            for (int k16 = 0; k16 < 4; ++k16) {
                int row = w * 16 + (q & 1) * 8 + r;
                int c = k16 * 2 + (q >> 1);
                ldsm4(qh[k16], sb + row * 128 + ((c ^ r) << 4));
            }
        }

        const uint32_t sk = sb + A_ST0 + buf * A_STAGE;
        const uint32_t sv = sk + 8192;
        const int j0 = jt * 64;
        const bool maskzone = (j0 + 63) > (i0 + w * 16);

        // ---- S = Q K^T over 64 keys (4 strips of 16) ----
        float s[8][4];
#pragma unroll
        for (int nt16 = 0; nt16 < 4; ++nt16) {
#pragma unroll
            for (int e = 0; e < 4; ++e) {
                s[2 * nt16][e] = 0.f;
                s[2 * nt16 + 1][e] = 0.f;
            }
            if (j0 + nt16 * 16 > rowlast) continue;  // fully masked strip
            const int row = nt16 * 16 + (q >> 1) * 8 + r;
#pragma unroll
            for (int k16 = 0; k16 < 4; ++k16) {
                const int c = k16 * 2 + (q & 1);
                uint32_t kh[4];
                ldsm4(kh, sk + row * 128 + ((c ^ r) << 4));
                mma16816(s[2 * nt16], qh[k16], kh);
                mma16816(s[2 * nt16 + 1], qh[k16], kh + 2);
            }
        }

        // ---- online softmax over this 64-key tile ----
        const int rowg0 = i0 + w * 16 + g;
        const int rowg1 = rowg0 + 8;
        float mx0 = -1e30f, mx1 = -1e30f;
#pragma unroll
        for (int nt = 0; nt < 8; ++nt) {
            const int jc = j0 + nt * 8 + 2 * t;
            const float c0 = (float)jc;
            s[nt][0] = s[nt][0] * 0.125f - slope * c0;
            s[nt][1] = s[nt][1] * 0.125f - slope * (c0 + 1.f);
            s[nt][2] = s[nt][2] * 0.125f - slope * c0;
            s[nt][3] = s[nt][3] * 0.125f - slope * (c0 + 1.f);
            if (maskzone) {
                if (jc > rowg0) s[nt][0] = -1e30f;
                if (jc + 1 > rowg0) s[nt][1] = -1e30f;
                if (jc > rowg1) s[nt][2] = -1e30f;
                if (jc + 1 > rowg1) s[nt][3] = -1e30f;
            }
            mx0 = fmaxf(mx0, fmaxf(s[nt][0], s[nt][1]));
            mx1 = fmaxf(mx1, fmaxf(s[nt][2], s[nt][3]));
        }
        mx0 = fmaxf(mx0, __shfl_xor_sync(0xffffffffu, mx0, 1, 4));
        mx0 = fmaxf(mx0, __shfl_xor_sync(0xffffffffu, mx0, 2, 4));
        mx1 = fmaxf(mx1, __shfl_xor_sync(0xffffffffu, mx1, 1, 4));
        mx1 = fmaxf(mx1, __shfl_xor_sync(0xffffffffu, mx1, 2, 4));
        const float mn0 = fmaxf(m0, mx0), mn1 = fmaxf(m1, mx1);
        const float cr0 = __expf(m0 - mn0), cr1 = __expf(m1 - mn1);
        m0 = mn0;
        m1 = mn1;
        float sum0 = 0.f, sum1 = 0.f;
#pragma unroll
        for (int nt = 0; nt < 8; ++nt) {
            s[nt][0] = __expf(s[nt][0] - mn0);
            s[nt][1] = __expf(s[nt][1] - mn0);
            s[nt][2] = __expf(s[nt][2] - mn1);
            s[nt][3] = __expf(s[nt][3] - mn1);
            sum0 += s[nt][0] + s[nt][1];
            sum1 += s[nt][2] + s[nt][3];
        }
        sum0 += __shfl_xor_sync(0xffffffffu, sum0, 1, 4);
        sum0 += __shfl_xor_sync(0xffffffffu, sum0, 2, 4);
        sum1 += __shfl_xor_sync(0xffffffffu, sum1, 1, 4);
        sum1 += __shfl_xor_sync(0xffffffffu, sum1, 2, 4);
        l0 = l0 * cr0 + sum0;
        l1 = l1 * cr1 + sum1;
#pragma unroll
        for (int nt = 0; nt < 8; ++nt) {
            o[nt][0] *= cr0;
            o[nt][1] *= cr0;
            o[nt][2] *= cr1;
            o[nt][3] *= cr1;
        }

        // ---- O += P V over 64 keys (4 k16 strips) ----
#pragma unroll
        for (int k16 = 0; k16 < 4; ++k16) {
            if (j0 + k16 * 16 > rowlast) continue;  // P strip exactly zero
            uint32_t ph[4];
            ph[0] = pack_f2h(s[2 * k16][0], s[2 * k16][1]);
            ph[1] = pack_f2h(s[2 * k16][2], s[2 * k16][3]);
            ph[2] = pack_f2h(s[2 * k16 + 1][0], s[2 * k16 + 1][1]);
            ph[3] = pack_f2h(s[2 * k16 + 1][2], s[2 * k16 + 1][3]);
            const int row = k16 * 16 + (q & 1) * 8 + r;
#pragma unroll
            for (int cgp = 0; cgp < 4; ++cgp) {
                const int c = cgp * 2 + (q >> 1);
                uint32_t vh[4];
                ldsm4t(vh, sv + row * 128 + ((c ^ r) << 4));
                mma16816(o[cgp * 2], ph, vh);
                mma16816(o[cgp * 2 + 1], ph, vh + 2);
            }
        }
        __syncthreads();
    }

    // ---- epilogue: normalize, store single fp16 ----
    const float inv0 = 1.f / l0, inv1 = 1.f / l1;
    const size_t orow0 = (size_t)(qrow_base + w * 16 + g) * DIM + hcol;
    const size_t orow1 = orow0 + (size_t)8 * DIM;
#pragma unroll
    for (int nt = 0; nt < 8; ++nt) {
        const int col = nt * 8 + 2 * t;
        *(uint32_t*)&gOh[orow0 + col] = pack_f2h(o[nt][0] * inv0, o[nt][1] * inv0);
        *(uint32_t*)&gOh[orow1 + col] = pack_f2h(o[nt][2] * inv1, o[nt][3] * inv1);
    }
}

// ---------------------------------------------------------------------------
extern "C" void kernel_launch(void* const* d_in, const int* in_sizes, int n_in,
                              void* d_out, int out_size) {
    const float* X  = (const float*)d_in[0];
    const float* Wq = (const float*)d_in[1];
    const float* bq = (const float*)d_in[2];
    const float* Wk = (const float*)d_in[3];
    const float* bk = (const float*)d_in[4];
    const float* Wv = (const float*)d_in[5];
    const float* Wo = (const float*)d_in[6];
    const float* bo = (const float*)d_in[7];
    float* out = (float*)d_out;

    cudaFuncSetAttribute(qkv_mma, cudaFuncAttributeMaxDynamicSharedMemorySize, GEMM_SMEM);
    cudaFuncSetAttribute(out_mma, cudaFuncAttributeMaxDynamicSharedMemorySize, GEMM_SMEM);
    cudaFuncSetAttribute(attn_mma, cudaFuncAttributeMaxDynamicSharedMemorySize, ATTN_SMEM);

    convert_inputs<<<2048, 256>>>(X, Wq, Wk, Wv, Wo);
    qkv_mma<<<dim3(DIM / 128, MROWS / 128, 3), 256, GEMM_SMEM>>>(bq, bk);
    attn_mma<<<dim3(SEQ / 128, BQ * NH), 256, ATTN_SMEM>>>();
    out_mma<<<dim3(DIM / 128, MROWS / 128, 1), 256, GEMM_SMEM>>>(bo, out);
}